// round 4
// baseline (speedup 1.0000x reference)
#include <cuda_runtime.h>
#include <cuda_fp16.h>
#include <math.h>
#include <stdint.h>

#define D_MODEL   2048
#define D_INNER   4096
#define D_STATE   128
#define HEADDIM   64
#define NHEADS    64
#define CONV_DIM  4352     /* D_INNER + 2*D_STATE */
#define D_IN_PROJ 8512     /* 2*D_INNER + 2*D_STATE + NHEADS */
#define BATCH     2
#define TLEN      2048
#define NTOK      (BATCH*TLEN)   /* 4096 */
#define RMS_EPS   1e-5f

// ---------------- scratch (device globals; no allocs allowed) ----------------
__device__ float g_zx [(size_t)NTOK * D_IN_PROJ];   // in_proj output
__device__ float g_xbc[(size_t)NTOK * CONV_DIM];    // conv+silu output
__device__ float g_y  [(size_t)NTOK * D_INNER];     // scan / gated+normed y

// fp16 hi/lo planes (hi plane then lo plane, each M*K halves)
__device__ __half g_xc [(size_t)2 * NTOK * D_MODEL];
__device__ __half g_w1c[(size_t)2 * D_IN_PROJ * D_MODEL];
__device__ __half g_yc [(size_t)2 * NTOK * D_INNER];
__device__ __half g_w2c[(size_t)2 * D_MODEL * D_INNER];

__device__ __forceinline__ uint32_t smem_to_u32(const void* p) {
    uint32_t a;
    asm("{ .reg .u64 t; cvta.to.shared.u64 t, %1; cvt.u32.u64 %0, t; }" : "=r"(a) : "l"(p));
    return a;
}

// ---------------- fp32 -> (hi, lo) fp16 planes ----------------
__global__ void __launch_bounds__(256) cvt_f16x2_kernel(
    const float* __restrict__ src, __half* __restrict__ hi, __half* __restrict__ lo, int n4)
{
    const int i = blockIdx.x * 256 + threadIdx.x;
    if (i >= n4) return;
    const float4 v = ((const float4*)src)[i];
    __half h0 = __float2half_rn(v.x), h1 = __float2half_rn(v.y);
    __half h2 = __float2half_rn(v.z), h3 = __float2half_rn(v.w);
    __half l0 = __float2half_rn(v.x - __half2float(h0));
    __half l1 = __float2half_rn(v.y - __half2float(h1));
    __half l2 = __float2half_rn(v.z - __half2float(h2));
    __half l3 = __float2half_rn(v.w - __half2float(h3));
    __half2* hp = (__half2*)(hi + (size_t)i * 4);
    __half2* lp = (__half2*)(lo + (size_t)i * 4);
    hp[0] = __halves2half2(h0, h1); hp[1] = __halves2half2(h2, h3);
    lp[0] = __halves2half2(l0, l1); lp[1] = __halves2half2(l2, l3);
}

// ======================= fp16x3 GEMM via mma.sync m16n8k16 =======================
// C[M,N] = A[M,K] * B[N,K]^T with A,B given as fp16 hi/lo planes.
// acc += Ahi*Bhi + Ahi*Blo + Alo*Bhi  (fp32 accumulate).
// 128x128x32 tile, 256 threads = 8 warps (2 M x 4 N), warp tile 64x32.
// Double-buffered SMEM via cp.async; rows padded to 40 halves (conflict-free).

#define PADH 40
#define TILE_H (128 * PADH)            /* 5120 halves per plane-tile */
#define STAGE_H (4 * TILE_H)           /* Ahi Alo Bhi Blo */
#define GEMM_SMEM (2 * STAGE_H * 2)    /* 2 stages, bytes = 81920 */

__device__ __forceinline__ void mma16816(float* c, const uint32_t* a, const uint32_t* b) {
    asm volatile(
        "mma.sync.aligned.m16n8k16.row.col.f32.f16.f16.f32 "
        "{%0,%1,%2,%3}, {%4,%5,%6,%7}, {%8,%9}, {%0,%1,%2,%3};"
        : "+f"(c[0]), "+f"(c[1]), "+f"(c[2]), "+f"(c[3])
        : "r"(a[0]), "r"(a[1]), "r"(a[2]), "r"(a[3]), "r"(b[0]), "r"(b[1]));
}

__global__ void __launch_bounds__(256, 1) mma_gemm_f16x3(
    const __half* __restrict__ Ahi, const __half* __restrict__ Alo,
    const __half* __restrict__ Bhi, const __half* __restrict__ Blo,
    float* __restrict__ C, int M, int N, int K)
{
    extern __shared__ __half sh[];
    const int tid  = threadIdx.x;
    const int wid  = tid >> 5;
    const int lane = tid & 31;
    const int g    = lane >> 2;
    const int tig  = lane & 3;
    const int bm   = blockIdx.x * 128;
    const int bn   = blockIdx.y * 128;
    const int wm   = (wid & 1) * 64;
    const int wn   = (wid >> 1) * 32;

    const uint32_t sbase = smem_to_u32(sh);

    float acc[4][4][4];
#pragma unroll
    for (int mt = 0; mt < 4; ++mt)
#pragma unroll
        for (int nt = 0; nt < 4; ++nt)
#pragma unroll
            for (int q = 0; q < 4; ++q) acc[mt][nt][q] = 0.f;

    const int NC = K >> 5;   // BK = 32

    auto load_stage = [&](int s, int c) {
        const int kb = c * 32;
#pragma unroll
        for (int i = 0; i < 2; ++i) {
            const int f   = tid + 256 * i;       // 0..511
            const int row = f >> 2;              // 0..127
            const int seg = (f & 3) * 8;         // halves: 0,8,16,24 (16B chunks)
            const uint32_t dst0 = sbase + (uint32_t)(s * STAGE_H + row * PADH + seg) * 2u;
            // A planes (rows always valid)
            {
                const __half* p = Ahi + (size_t)(bm + row) * K + kb + seg;
                asm volatile("cp.async.cg.shared.global [%0], [%1], 16;"
                             :: "r"(dst0), "l"(p) : "memory");
                const __half* q2 = Alo + (size_t)(bm + row) * K + kb + seg;
                asm volatile("cp.async.cg.shared.global [%0], [%1], 16;"
                             :: "r"(dst0 + TILE_H * 2u), "l"(q2) : "memory");
            }
            // B planes (row guard with zero fill)
            {
                const int brow = bn + row;
                const int safe = (brow < N) ? brow : 0;
                const uint32_t sz = (brow < N) ? 16u : 0u;
                const __half* p = Bhi + (size_t)safe * K + kb + seg;
                asm volatile("cp.async.cg.shared.global [%0], [%1], 16, %2;"
                             :: "r"(dst0 + 2u * TILE_H * 2u), "l"(p), "r"(sz) : "memory");
                const __half* q2 = Blo + (size_t)safe * K + kb + seg;
                asm volatile("cp.async.cg.shared.global [%0], [%1], 16, %2;"
                             :: "r"(dst0 + 3u * TILE_H * 2u), "l"(q2), "r"(sz) : "memory");
            }
        }
        asm volatile("cp.async.commit_group;" ::: "memory");
    };

    auto compute_stage = [&](int s) {
        const __half* Ah_ = sh + s * STAGE_H;
        const __half* Al_ = Ah_ + TILE_H;
        const __half* Bh_ = Ah_ + 2 * TILE_H;
        const __half* Bl_ = Ah_ + 3 * TILE_H;
#pragma unroll
        for (int ks = 0; ks < 2; ++ks) {
            const int k0 = ks * 16 + 2 * tig;
            uint32_t ah[4][4], al[4][4];
#pragma unroll
            for (int mt = 0; mt < 4; ++mt) {
                const int r = wm + mt * 16 + g;
                ah[mt][0] = *(const uint32_t*)(Ah_ + r * PADH + k0);
                ah[mt][1] = *(const uint32_t*)(Ah_ + (r + 8) * PADH + k0);
                ah[mt][2] = *(const uint32_t*)(Ah_ + r * PADH + k0 + 8);
                ah[mt][3] = *(const uint32_t*)(Ah_ + (r + 8) * PADH + k0 + 8);
                al[mt][0] = *(const uint32_t*)(Al_ + r * PADH + k0);
                al[mt][1] = *(const uint32_t*)(Al_ + (r + 8) * PADH + k0);
                al[mt][2] = *(const uint32_t*)(Al_ + r * PADH + k0 + 8);
                al[mt][3] = *(const uint32_t*)(Al_ + (r + 8) * PADH + k0 + 8);
            }
            uint32_t bh[4][2], bl[4][2];
#pragma unroll
            for (int nt = 0; nt < 4; ++nt) {
                const int r = wn + nt * 8 + g;
                bh[nt][0] = *(const uint32_t*)(Bh_ + r * PADH + k0);
                bh[nt][1] = *(const uint32_t*)(Bh_ + r * PADH + k0 + 8);
                bl[nt][0] = *(const uint32_t*)(Bl_ + r * PADH + k0);
                bl[nt][1] = *(const uint32_t*)(Bl_ + r * PADH + k0 + 8);
            }
#pragma unroll
            for (int mt = 0; mt < 4; ++mt)
#pragma unroll
                for (int nt = 0; nt < 4; ++nt) {
                    mma16816(acc[mt][nt], ah[mt], bh[nt]);
                    mma16816(acc[mt][nt], ah[mt], bl[nt]);
                    mma16816(acc[mt][nt], al[mt], bh[nt]);
                }
        }
    };

    load_stage(0, 0);
    for (int c = 0; c < NC; ++c) {
        if (c + 1 < NC) {
            load_stage((c + 1) & 1, c + 1);
            asm volatile("cp.async.wait_group 1;" ::: "memory");
        } else {
            asm volatile("cp.async.wait_group 0;" ::: "memory");
        }
        __syncthreads();
        compute_stage(c & 1);
        __syncthreads();
    }

#pragma unroll
    for (int mt = 0; mt < 4; ++mt) {
        const int row0 = bm + wm + mt * 16 + g;
#pragma unroll
        for (int nt = 0; nt < 4; ++nt) {
            const int col = bn + wn + nt * 8 + tig * 2;
            if (col < N) {
                *(float2*)(C + (size_t)row0 * N + col)       = make_float2(acc[mt][nt][0], acc[mt][nt][1]);
                *(float2*)(C + (size_t)(row0 + 8) * N + col) = make_float2(acc[mt][nt][2], acc[mt][nt][3]);
            }
        }
    }
}

// ---------------- depthwise causal conv (width 4) + SiLU ----------------
__global__ void __launch_bounds__(256) conv_silu_kernel(
    const float* __restrict__ cw, const float* __restrict__ cb)
{
    const int c  = blockIdx.x * 256 + threadIdx.x;
    const int b  = blockIdx.z;
    const int t0 = blockIdx.y * 32;

    const float w0 = cw[c*4+0], w1 = cw[c*4+1], w2 = cw[c*4+2], w3 = cw[c*4+3];
    const float bias = cb[c];

    const float* base = g_zx + ((size_t)b * TLEN) * D_IN_PROJ + D_INNER + c;
    float* ob = g_xbc + ((size_t)b * TLEN) * CONV_DIM + c;

    float x0 = (t0 >= 3) ? base[(size_t)(t0-3) * D_IN_PROJ] : 0.f;
    float x1 = (t0 >= 2) ? base[(size_t)(t0-2) * D_IN_PROJ] : 0.f;
    float x2 = (t0 >= 1) ? base[(size_t)(t0-1) * D_IN_PROJ] : 0.f;

    for (int t = t0; t < t0 + 32; ++t) {
        const float x3 = base[(size_t)t * D_IN_PROJ];
        const float v  = bias + x0*w0 + x1*w1 + x2*w2 + x3*w3;
        ob[(size_t)t * CONV_DIM] = v / (1.f + expf(-v));
        x0 = x1; x1 = x2; x2 = x3;
    }
}

// ---------------- SSM scan (256 threads: thread owns 32 states) ----------------
#define SCAN_TC 8
__global__ void __launch_bounds__(256) scan_kernel(
    const float* __restrict__ dt_bias, const float* __restrict__ A_log,
    const float* __restrict__ Dskip)
{
    const int h   = blockIdx.x;
    const int b   = blockIdx.y;
    const int tid = threadIdx.x;
    const int p   = tid >> 2;        // head-dim element 0..63
    const int q   = tid & 3;         // state quarter
    const int nb  = q * 32;

    __shared__ __align__(16) float sB[SCAN_TC][128];
    __shared__ __align__(16) float sC[SCAN_TC][128];
    __shared__ __align__(16) float sX[SCAN_TC][64];
    __shared__ float sDA[SCAN_TC], sDT[SCAN_TC];

    float4 hst[8];
#pragma unroll
    for (int r = 0; r < 8; ++r) hst[r] = make_float4(0.f,0.f,0.f,0.f);

    const float Acoef = -expf(A_log[h]);
    const float dtb   = dt_bias[h];
    const float dsk   = Dskip[h];

    const float* xbc_b    = g_xbc + (size_t)b * TLEN * CONV_DIM;
    const float* dtr_base = g_zx  + (size_t)b * TLEN * D_IN_PROJ + (D_INNER + CONV_DIM) + h;
    float*       y_base   = g_y   + (size_t)b * TLEN * D_INNER + h * HEADDIM;

    for (int t0 = 0; t0 < TLEN; t0 += SCAN_TC) {
        for (int i = tid; i < SCAN_TC * 128; i += 256) {
            const int tl = i >> 7, c = i & 127;
            const float* row = xbc_b + (size_t)(t0 + tl) * CONV_DIM + D_INNER;
            sB[tl][c] = row[c];
            sC[tl][c] = row[D_STATE + c];
        }
        for (int i = tid; i < SCAN_TC * 64; i += 256) {
            const int tl = i >> 6, c = i & 63;
            sX[tl][c] = xbc_b[(size_t)(t0 + tl) * CONV_DIM + h * HEADDIM + c];
        }
        if (tid < SCAN_TC) {
            const float raw = dtr_base[(size_t)(t0 + tid) * D_IN_PROJ] + dtb;
            const float dt  = (raw > 20.f) ? raw : log1pf(expf(raw));
            sDT[tid] = dt;
            sDA[tid] = expf(dt * Acoef);
        }
        __syncthreads();

#pragma unroll
        for (int tl = 0; tl < SCAN_TC; ++tl) {
            const float dA  = sDA[tl];
            const float dtx = sDT[tl] * sX[tl][p];
            const float4* B4 = (const float4*)&sB[tl][nb];
            const float4* C4 = (const float4*)&sC[tl][nb];
            float y = 0.f;
#pragma unroll
            for (int r = 0; r < 8; ++r) {
                const float4 bb = B4[r];
                const float4 cc = C4[r];
                hst[r].x = hst[r].x * dA + dtx * bb.x;  y += hst[r].x * cc.x;
                hst[r].y = hst[r].y * dA + dtx * bb.y;  y += hst[r].y * cc.y;
                hst[r].z = hst[r].z * dA + dtx * bb.z;  y += hst[r].z * cc.z;
                hst[r].w = hst[r].w * dA + dtx * bb.w;  y += hst[r].w * cc.w;
            }
            y += __shfl_xor_sync(0xffffffffu, y, 1);
            y += __shfl_xor_sync(0xffffffffu, y, 2);
            if (q == 0) {
                y += dsk * sX[tl][p];
                y_base[(size_t)(t0 + tl) * D_INNER + p] = y;
            }
        }
        __syncthreads();
    }
}

// ---------------- gate (y * silu(z)) + RMSNorm, in place on g_y ----------------
__global__ void __launch_bounds__(256) gate_norm_kernel(const float* __restrict__ nw)
{
    const int row = blockIdx.x;
    const int tid = threadIdx.x;
    const float* zrow = g_zx + (size_t)row * D_IN_PROJ;
    float*       yrow = g_y  + (size_t)row * D_INNER;

    float g[16];
    float ss = 0.f;
#pragma unroll
    for (int i = 0; i < 4; ++i) {
        const int e = i * 1024 + tid * 4;
        const float4 yv = *(const float4*)(yrow + e);
        const float4 zv = *(const float4*)(zrow + e);
        float g0 = yv.x * (zv.x / (1.f + expf(-zv.x)));
        float g1 = yv.y * (zv.y / (1.f + expf(-zv.y)));
        float g2 = yv.z * (zv.z / (1.f + expf(-zv.z)));
        float g3 = yv.w * (zv.w / (1.f + expf(-zv.w)));
        g[i*4+0] = g0; g[i*4+1] = g1; g[i*4+2] = g2; g[i*4+3] = g3;
        ss += g0*g0 + g1*g1 + g2*g2 + g3*g3;
    }

    ss += __shfl_xor_sync(0xffffffffu, ss, 16);
    ss += __shfl_xor_sync(0xffffffffu, ss, 8);
    ss += __shfl_xor_sync(0xffffffffu, ss, 4);
    ss += __shfl_xor_sync(0xffffffffu, ss, 2);
    ss += __shfl_xor_sync(0xffffffffu, ss, 1);
    __shared__ float red[8];
    if ((tid & 31) == 0) red[tid >> 5] = ss;
    __syncthreads();
    float tot = 0.f;
#pragma unroll
    for (int w = 0; w < 8; ++w) tot += red[w];

    const float scale = rsqrtf(tot / (float)D_INNER + RMS_EPS);
#pragma unroll
    for (int i = 0; i < 4; ++i) {
        const int e = i * 1024 + tid * 4;
        float4 o;
        o.x = g[i*4+0] * scale * nw[e+0];
        o.y = g[i*4+1] * scale * nw[e+1];
        o.z = g[i*4+2] * scale * nw[e+2];
        o.w = g[i*4+3] * scale * nw[e+3];
        *(float4*)(yrow + e) = o;
    }
}

// ---------------- launch ----------------
extern "C" void kernel_launch(void* const* d_in, const int* in_sizes, int n_in,
                              void* d_out, int out_size)
{
    const float* x          = (const float*)d_in[0];
    const float* in_proj_w  = (const float*)d_in[3];
    const float* conv_w     = (const float*)d_in[4];
    const float* conv_b     = (const float*)d_in[5];
    const float* dt_bias    = (const float*)d_in[6];
    const float* A_log      = (const float*)d_in[7];
    const float* Dskip      = (const float*)d_in[8];
    const float* norm_w     = (const float*)d_in[9];
    const float* out_proj_w = (const float*)d_in[10];
    float* out = (float*)d_out;

    float *zx, *y;
    __half *xc, *w1c, *yc, *w2c;
    cudaGetSymbolAddress((void**)&zx,  g_zx);
    cudaGetSymbolAddress((void**)&y,   g_y);
    cudaGetSymbolAddress((void**)&xc,  g_xc);
    cudaGetSymbolAddress((void**)&w1c, g_w1c);
    cudaGetSymbolAddress((void**)&yc,  g_yc);
    cudaGetSymbolAddress((void**)&w2c, g_w2c);

    cudaFuncSetAttribute(mma_gemm_f16x3,
                         cudaFuncAttributeMaxDynamicSharedMemorySize, GEMM_SMEM);

    // 0) convert x and weights to fp16 hi/lo planes
    {
        const int nx = NTOK * D_MODEL / 4;
        cvt_f16x2_kernel<<<(nx + 255) / 256, 256>>>(x, xc, xc + (size_t)NTOK * D_MODEL, nx);
        const int nw1 = D_IN_PROJ * D_MODEL / 4;
        cvt_f16x2_kernel<<<(nw1 + 255) / 256, 256>>>(in_proj_w, w1c, w1c + (size_t)D_IN_PROJ * D_MODEL, nw1);
        const int nw2 = D_MODEL * D_INNER / 4;
        cvt_f16x2_kernel<<<(nw2 + 255) / 256, 256>>>(out_proj_w, w2c, w2c + (size_t)D_MODEL * D_INNER, nw2);
    }

    // 1) in_proj: zx[4096, 8512] = x * W1^T
    {
        dim3 grid(NTOK / 128, (D_IN_PROJ + 127) / 128);
        mma_gemm_f16x3<<<grid, 256, GEMM_SMEM>>>(
            xc, xc + (size_t)NTOK * D_MODEL,
            w1c, w1c + (size_t)D_IN_PROJ * D_MODEL,
            zx, NTOK, D_IN_PROJ, D_MODEL);
    }
    // 2) conv + silu
    {
        dim3 grid(CONV_DIM / 256, TLEN / 32, BATCH);
        conv_silu_kernel<<<grid, 256>>>(conv_w, conv_b);
    }
    // 3) SSM scan
    {
        dim3 grid(NHEADS, BATCH);
        scan_kernel<<<grid, 256>>>(dt_bias, A_log, Dskip);
    }
    // 4) gate + RMSNorm
    gate_norm_kernel<<<NTOK, 256>>>(norm_w);

    // 4.5) convert y
    {
        const int ny = NTOK * D_INNER / 4;
        cvt_f16x2_kernel<<<(ny + 255) / 256, 256>>>(y, yc, yc + (size_t)NTOK * D_INNER, ny);
    }

    // 5) out_proj: out[4096, 2048] = y * W2^T
    {
        dim3 grid(NTOK / 128, D_MODEL / 128);
        mma_gemm_f16x3<<<grid, 256, GEMM_SMEM>>>(
            yc, yc + (size_t)NTOK * D_INNER,
            w2c, w2c + (size_t)D_MODEL * D_INNER,
            out, NTOK, D_MODEL, D_INNER);
    }
}

// round 5
// speedup vs baseline: 1.0063x; 1.0063x over previous
#include <cuda_runtime.h>
#include <cuda_fp16.h>
#include <math.h>
#include <stdint.h>

#define D_MODEL   2048
#define D_INNER   4096
#define D_STATE   128
#define HEADDIM   64
#define NHEADS    64
#define CONV_DIM  4352     /* D_INNER + 2*D_STATE */
#define D_IN_PROJ 8512     /* 2*D_INNER + 2*D_STATE + NHEADS */
#define BATCH     2
#define TLEN      2048
#define NTOK      (BATCH*TLEN)   /* 4096 */
#define RMS_EPS   1e-5f

// ---------------- scratch (device globals; no allocs allowed) ----------------
__device__ float g_zx [(size_t)NTOK * D_IN_PROJ];   // in_proj output
__device__ float g_xbc[(size_t)NTOK * CONV_DIM];    // conv+silu output
__device__ float g_y  [(size_t)NTOK * D_INNER];     // scan / gated+normed y

// fp16 hi/lo planes (hi plane then lo plane)
__device__ __half g_xc [(size_t)2 * NTOK * D_MODEL];
__device__ __half g_w1c[(size_t)2 * D_IN_PROJ * D_MODEL];
__device__ __half g_yc [(size_t)2 * NTOK * D_INNER];
__device__ __half g_w2c[(size_t)2 * D_MODEL * D_INNER];

__device__ __forceinline__ uint32_t smem_to_u32(const void* p) {
    uint32_t a;
    asm("{ .reg .u64 t; cvta.to.shared.u64 t, %1; cvt.u32.u64 %0, t; }" : "=r"(a) : "l"(p));
    return a;
}

// ---------------- fp32 -> (hi, lo) fp16 planes ----------------
__global__ void __launch_bounds__(256) cvt_f16x2_kernel(
    const float* __restrict__ src, __half* __restrict__ hi, __half* __restrict__ lo, int n4)
{
    const int i = blockIdx.x * 256 + threadIdx.x;
    if (i >= n4) return;
    const float4 v = ((const float4*)src)[i];
    __half h0 = __float2half_rn(v.x), h1 = __float2half_rn(v.y);
    __half h2 = __float2half_rn(v.z), h3 = __float2half_rn(v.w);
    __half l0 = __float2half_rn(v.x - __half2float(h0));
    __half l1 = __float2half_rn(v.y - __half2float(h1));
    __half l2 = __float2half_rn(v.z - __half2float(h2));
    __half l3 = __float2half_rn(v.w - __half2float(h3));
    __half2* hp = (__half2*)(hi + (size_t)i * 4);
    __half2* lp = (__half2*)(lo + (size_t)i * 4);
    hp[0] = __halves2half2(h0, h1); hp[1] = __halves2half2(h2, h3);
    lp[0] = __halves2half2(l0, l1); lp[1] = __halves2half2(l2, l3);
}

// ======================= fp16x3 GEMM, 128x256 tile, 512 threads =======================
// C[M,N] = A[M,K] * B[N,K]^T ; acc += Ahi*Bhi + Ahi*Blo + Alo*Bhi (fp32 accumulate).
// 16 warps = 2 M x 8 N, warp tile 64x32. BK=32, double-buffered cp.async.

#define PADH 40
#define A_TILE_H (128 * PADH)                  /* 5120 halves */
#define B_TILE_H (256 * PADH)                  /* 10240 halves */
#define STAGE_H  (2 * A_TILE_H + 2 * B_TILE_H) /* 30720 halves = 61440 B */
#define GEMM_SMEM (2 * STAGE_H * 2)            /* 122880 B */

__device__ __forceinline__ void mma16816(float* c, const uint32_t* a, const uint32_t* b) {
    asm volatile(
        "mma.sync.aligned.m16n8k16.row.col.f32.f16.f16.f32 "
        "{%0,%1,%2,%3}, {%4,%5,%6,%7}, {%8,%9}, {%0,%1,%2,%3};"
        : "+f"(c[0]), "+f"(c[1]), "+f"(c[2]), "+f"(c[3])
        : "r"(a[0]), "r"(a[1]), "r"(a[2]), "r"(a[3]), "r"(b[0]), "r"(b[1]));
}

__global__ void __launch_bounds__(512, 1) mma_gemm_f16x3(
    const __half* __restrict__ Ahi, const __half* __restrict__ Alo,
    const __half* __restrict__ Bhi, const __half* __restrict__ Blo,
    float* __restrict__ C, int M, int N, int K)
{
    extern __shared__ __half sh[];
    const int tid  = threadIdx.x;
    const int wid  = tid >> 5;
    const int lane = tid & 31;
    const int g    = lane >> 2;
    const int tig  = lane & 3;
    const int bm   = blockIdx.x * 128;
    const int bn   = blockIdx.y * 256;
    const int wm   = (wid & 1) * 64;
    const int wn   = (wid >> 1) * 32;

    const uint32_t sbase = smem_to_u32(sh);

    float acc[4][4][4];
#pragma unroll
    for (int mt = 0; mt < 4; ++mt)
#pragma unroll
        for (int nt = 0; nt < 4; ++nt)
#pragma unroll
            for (int q = 0; q < 4; ++q) acc[mt][nt][q] = 0.f;

    const int NC = K >> 5;   // BK = 32

    auto load_stage = [&](int s, int c) {
        const int kb = c * 32;
        const uint32_t stg = sbase + (uint32_t)s * STAGE_H * 2u;
        // A planes: 512 chunks of 16B each (row 0..127, 4 chunks/row)
        {
            const int row = tid >> 2;
            const int seg = (tid & 3) * 8;
            const uint32_t dst = stg + (uint32_t)(row * PADH + seg) * 2u;
            const __half* p  = Ahi + (size_t)(bm + row) * K + kb + seg;
            asm volatile("cp.async.cg.shared.global [%0], [%1], 16;"
                         :: "r"(dst), "l"(p) : "memory");
            const __half* q2 = Alo + (size_t)(bm + row) * K + kb + seg;
            asm volatile("cp.async.cg.shared.global [%0], [%1], 16;"
                         :: "r"(dst + A_TILE_H * 2u), "l"(q2) : "memory");
        }
        // B planes: 1024 chunks each (row 0..255, 4 chunks/row), 2 iters
#pragma unroll
        for (int i = 0; i < 2; ++i) {
            const int f   = tid + 512 * i;
            const int row = f >> 2;
            const int seg = (f & 3) * 8;
            const int brow = bn + row;
            const int safe = (brow < N) ? brow : 0;
            const uint32_t sz = (brow < N) ? 16u : 0u;
            const uint32_t dst = stg + (uint32_t)(2 * A_TILE_H + row * PADH + seg) * 2u;
            const __half* p  = Bhi + (size_t)safe * K + kb + seg;
            asm volatile("cp.async.cg.shared.global [%0], [%1], 16, %2;"
                         :: "r"(dst), "l"(p), "r"(sz) : "memory");
            const __half* q2 = Blo + (size_t)safe * K + kb + seg;
            asm volatile("cp.async.cg.shared.global [%0], [%1], 16, %2;"
                         :: "r"(dst + B_TILE_H * 2u), "l"(q2), "r"(sz) : "memory");
        }
        asm volatile("cp.async.commit_group;" ::: "memory");
    };

    auto compute_stage = [&](int s) {
        const __half* Ah_ = sh + (size_t)s * STAGE_H;
        const __half* Al_ = Ah_ + A_TILE_H;
        const __half* Bh_ = Ah_ + 2 * A_TILE_H;
        const __half* Bl_ = Bh_ + B_TILE_H;
#pragma unroll
        for (int ks = 0; ks < 2; ++ks) {
            const int k0 = ks * 16 + 2 * tig;
            // B fragments for this warp's 32 columns
            uint32_t bh[4][2], bl[4][2];
#pragma unroll
            for (int nt = 0; nt < 4; ++nt) {
                const int r = wn + nt * 8 + g;
                bh[nt][0] = *(const uint32_t*)(Bh_ + r * PADH + k0);
                bh[nt][1] = *(const uint32_t*)(Bh_ + r * PADH + k0 + 8);
                bl[nt][0] = *(const uint32_t*)(Bl_ + r * PADH + k0);
                bl[nt][1] = *(const uint32_t*)(Bl_ + r * PADH + k0 + 8);
            }
            // A fragments loaded just-in-time per mt to bound register pressure
#pragma unroll
            for (int mt = 0; mt < 4; ++mt) {
                const int r = wm + mt * 16 + g;
                uint32_t ah[4], al[4];
                ah[0] = *(const uint32_t*)(Ah_ + r * PADH + k0);
                ah[1] = *(const uint32_t*)(Ah_ + (r + 8) * PADH + k0);
                ah[2] = *(const uint32_t*)(Ah_ + r * PADH + k0 + 8);
                ah[3] = *(const uint32_t*)(Ah_ + (r + 8) * PADH + k0 + 8);
                al[0] = *(const uint32_t*)(Al_ + r * PADH + k0);
                al[1] = *(const uint32_t*)(Al_ + (r + 8) * PADH + k0);
                al[2] = *(const uint32_t*)(Al_ + r * PADH + k0 + 8);
                al[3] = *(const uint32_t*)(Al_ + (r + 8) * PADH + k0 + 8);
#pragma unroll
                for (int nt = 0; nt < 4; ++nt) {
                    mma16816(acc[mt][nt], ah, bh[nt]);
                    mma16816(acc[mt][nt], ah, bl[nt]);
                    mma16816(acc[mt][nt], al, bh[nt]);
                }
            }
        }
    };

    load_stage(0, 0);
    for (int c = 0; c < NC; ++c) {
        if (c + 1 < NC) {
            load_stage((c + 1) & 1, c + 1);
            asm volatile("cp.async.wait_group 1;" ::: "memory");
        } else {
            asm volatile("cp.async.wait_group 0;" ::: "memory");
        }
        __syncthreads();
        compute_stage(c & 1);
        __syncthreads();
    }

#pragma unroll
    for (int mt = 0; mt < 4; ++mt) {
        const int row0 = bm + wm + mt * 16 + g;
#pragma unroll
        for (int nt = 0; nt < 4; ++nt) {
            const int col = bn + wn + nt * 8 + tig * 2;
            if (col < N) {
                *(float2*)(C + (size_t)row0 * N + col)       = make_float2(acc[mt][nt][0], acc[mt][nt][1]);
                *(float2*)(C + (size_t)(row0 + 8) * N + col) = make_float2(acc[mt][nt][2], acc[mt][nt][3]);
            }
        }
    }
}

// ---------------- depthwise causal conv (width 4) + SiLU ----------------
__global__ void __launch_bounds__(256) conv_silu_kernel(
    const float* __restrict__ cw, const float* __restrict__ cb)
{
    const int c  = blockIdx.x * 256 + threadIdx.x;
    const int b  = blockIdx.z;
    const int t0 = blockIdx.y * 32;

    const float w0 = cw[c*4+0], w1 = cw[c*4+1], w2 = cw[c*4+2], w3 = cw[c*4+3];
    const float bias = cb[c];

    const float* base = g_zx + ((size_t)b * TLEN) * D_IN_PROJ + D_INNER + c;
    float* ob = g_xbc + ((size_t)b * TLEN) * CONV_DIM + c;

    float x0 = (t0 >= 3) ? base[(size_t)(t0-3) * D_IN_PROJ] : 0.f;
    float x1 = (t0 >= 2) ? base[(size_t)(t0-2) * D_IN_PROJ] : 0.f;
    float x2 = (t0 >= 1) ? base[(size_t)(t0-1) * D_IN_PROJ] : 0.f;

    for (int t = t0; t < t0 + 32; ++t) {
        const float x3 = base[(size_t)t * D_IN_PROJ];
        const float v  = bias + x0*w0 + x1*w1 + x2*w2 + x3*w3;
        ob[(size_t)t * CONV_DIM] = v / (1.f + expf(-v));
        x0 = x1; x1 = x2; x2 = x3;
    }
}

// ---------------- SSM scan (256 threads: thread owns 32 states) ----------------
#define SCAN_TC 8
__global__ void __launch_bounds__(256) scan_kernel(
    const float* __restrict__ dt_bias, const float* __restrict__ A_log,
    const float* __restrict__ Dskip)
{
    const int h   = blockIdx.x;
    const int b   = blockIdx.y;
    const int tid = threadIdx.x;
    const int p   = tid >> 2;        // head-dim element 0..63
    const int q   = tid & 3;         // state quarter
    const int nb  = q * 32;

    __shared__ __align__(16) float sB[SCAN_TC][128];
    __shared__ __align__(16) float sC[SCAN_TC][128];
    __shared__ __align__(16) float sX[SCAN_TC][64];
    __shared__ float sDA[SCAN_TC], sDT[SCAN_TC];

    float4 hst[8];
#pragma unroll
    for (int r = 0; r < 8; ++r) hst[r] = make_float4(0.f,0.f,0.f,0.f);

    const float Acoef = -expf(A_log[h]);
    const float dtb   = dt_bias[h];
    const float dsk   = Dskip[h];

    const float* xbc_b    = g_xbc + (size_t)b * TLEN * CONV_DIM;
    const float* dtr_base = g_zx  + (size_t)b * TLEN * D_IN_PROJ + (D_INNER + CONV_DIM) + h;
    float*       y_base   = g_y   + (size_t)b * TLEN * D_INNER + h * HEADDIM;

    for (int t0 = 0; t0 < TLEN; t0 += SCAN_TC) {
        for (int i = tid; i < SCAN_TC * 128; i += 256) {
            const int tl = i >> 7, c = i & 127;
            const float* row = xbc_b + (size_t)(t0 + tl) * CONV_DIM + D_INNER;
            sB[tl][c] = row[c];
            sC[tl][c] = row[D_STATE + c];
        }
        for (int i = tid; i < SCAN_TC * 64; i += 256) {
            const int tl = i >> 6, c = i & 63;
            sX[tl][c] = xbc_b[(size_t)(t0 + tl) * CONV_DIM + h * HEADDIM + c];
        }
        if (tid < SCAN_TC) {
            const float raw = dtr_base[(size_t)(t0 + tid) * D_IN_PROJ] + dtb;
            const float dt  = (raw > 20.f) ? raw : log1pf(expf(raw));
            sDT[tid] = dt;
            sDA[tid] = expf(dt * Acoef);
        }
        __syncthreads();

#pragma unroll
        for (int tl = 0; tl < SCAN_TC; ++tl) {
            const float dA  = sDA[tl];
            const float dtx = sDT[tl] * sX[tl][p];
            const float4* B4 = (const float4*)&sB[tl][nb];
            const float4* C4 = (const float4*)&sC[tl][nb];
            float y = 0.f;
#pragma unroll
            for (int r = 0; r < 8; ++r) {
                const float4 bb = B4[r];
                const float4 cc = C4[r];
                hst[r].x = hst[r].x * dA + dtx * bb.x;  y += hst[r].x * cc.x;
                hst[r].y = hst[r].y * dA + dtx * bb.y;  y += hst[r].y * cc.y;
                hst[r].z = hst[r].z * dA + dtx * bb.z;  y += hst[r].z * cc.z;
                hst[r].w = hst[r].w * dA + dtx * bb.w;  y += hst[r].w * cc.w;
            }
            y += __shfl_xor_sync(0xffffffffu, y, 1);
            y += __shfl_xor_sync(0xffffffffu, y, 2);
            if (q == 0) {
                y += dsk * sX[tl][p];
                y_base[(size_t)(t0 + tl) * D_INNER + p] = y;
            }
        }
        __syncthreads();
    }
}

// ---------------- gate (y * silu(z)) + RMSNorm, in place on g_y ----------------
__global__ void __launch_bounds__(256) gate_norm_kernel(const float* __restrict__ nw)
{
    const int row = blockIdx.x;
    const int tid = threadIdx.x;
    const float* zrow = g_zx + (size_t)row * D_IN_PROJ;
    float*       yrow = g_y  + (size_t)row * D_INNER;

    float g[16];
    float ss = 0.f;
#pragma unroll
    for (int i = 0; i < 4; ++i) {
        const int e = i * 1024 + tid * 4;
        const float4 yv = *(const float4*)(yrow + e);
        const float4 zv = *(const float4*)(zrow + e);
        float g0 = yv.x * (zv.x / (1.f + expf(-zv.x)));
        float g1 = yv.y * (zv.y / (1.f + expf(-zv.y)));
        float g2 = yv.z * (zv.z / (1.f + expf(-zv.z)));
        float g3 = yv.w * (zv.w / (1.f + expf(-zv.w)));
        g[i*4+0] = g0; g[i*4+1] = g1; g[i*4+2] = g2; g[i*4+3] = g3;
        ss += g0*g0 + g1*g1 + g2*g2 + g3*g3;
    }

    ss += __shfl_xor_sync(0xffffffffu, ss, 16);
    ss += __shfl_xor_sync(0xffffffffu, ss, 8);
    ss += __shfl_xor_sync(0xffffffffu, ss, 4);
    ss += __shfl_xor_sync(0xffffffffu, ss, 2);
    ss += __shfl_xor_sync(0xffffffffu, ss, 1);
    __shared__ float red[8];
    if ((tid & 31) == 0) red[tid >> 5] = ss;
    __syncthreads();
    float tot = 0.f;
#pragma unroll
    for (int w = 0; w < 8; ++w) tot += red[w];

    const float scale = rsqrtf(tot / (float)D_INNER + RMS_EPS);
#pragma unroll
    for (int i = 0; i < 4; ++i) {
        const int e = i * 1024 + tid * 4;
        float4 o;
        o.x = g[i*4+0] * scale * nw[e+0];
        o.y = g[i*4+1] * scale * nw[e+1];
        o.z = g[i*4+2] * scale * nw[e+2];
        o.w = g[i*4+3] * scale * nw[e+3];
        *(float4*)(yrow + e) = o;
    }
}

// ---------------- launch ----------------
extern "C" void kernel_launch(void* const* d_in, const int* in_sizes, int n_in,
                              void* d_out, int out_size)
{
    const float* x          = (const float*)d_in[0];
    const float* in_proj_w  = (const float*)d_in[3];
    const float* conv_w     = (const float*)d_in[4];
    const float* conv_b     = (const float*)d_in[5];
    const float* dt_bias    = (const float*)d_in[6];
    const float* A_log      = (const float*)d_in[7];
    const float* Dskip      = (const float*)d_in[8];
    const float* norm_w     = (const float*)d_in[9];
    const float* out_proj_w = (const float*)d_in[10];
    float* out = (float*)d_out;

    float *zx, *y;
    __half *xc, *w1c, *yc, *w2c;
    cudaGetSymbolAddress((void**)&zx,  g_zx);
    cudaGetSymbolAddress((void**)&y,   g_y);
    cudaGetSymbolAddress((void**)&xc,  g_xc);
    cudaGetSymbolAddress((void**)&w1c, g_w1c);
    cudaGetSymbolAddress((void**)&yc,  g_yc);
    cudaGetSymbolAddress((void**)&w2c, g_w2c);

    cudaFuncSetAttribute(mma_gemm_f16x3,
                         cudaFuncAttributeMaxDynamicSharedMemorySize, GEMM_SMEM);

    // 0) convert x and weights to fp16 hi/lo planes
    {
        const int nx = NTOK * D_MODEL / 4;
        cvt_f16x2_kernel<<<(nx + 255) / 256, 256>>>(x, xc, xc + (size_t)NTOK * D_MODEL, nx);
        const int nw1 = D_IN_PROJ * D_MODEL / 4;
        cvt_f16x2_kernel<<<(nw1 + 255) / 256, 256>>>(in_proj_w, w1c, w1c + (size_t)D_IN_PROJ * D_MODEL, nw1);
        const int nw2 = D_MODEL * D_INNER / 4;
        cvt_f16x2_kernel<<<(nw2 + 255) / 256, 256>>>(out_proj_w, w2c, w2c + (size_t)D_MODEL * D_INNER, nw2);
    }

    // 1) in_proj: zx[4096, 8512] = x * W1^T
    {
        dim3 grid(NTOK / 128, (D_IN_PROJ + 255) / 256);
        mma_gemm_f16x3<<<grid, 512, GEMM_SMEM>>>(
            xc, xc + (size_t)NTOK * D_MODEL,
            w1c, w1c + (size_t)D_IN_PROJ * D_MODEL,
            zx, NTOK, D_IN_PROJ, D_MODEL);
    }
    // 2) conv + silu
    {
        dim3 grid(CONV_DIM / 256, TLEN / 32, BATCH);
        conv_silu_kernel<<<grid, 256>>>(conv_w, conv_b);
    }
    // 3) SSM scan
    {
        dim3 grid(NHEADS, BATCH);
        scan_kernel<<<grid, 256>>>(dt_bias, A_log, Dskip);
    }
    // 4) gate + RMSNorm
    gate_norm_kernel<<<NTOK, 256>>>(norm_w);

    // 4.5) convert y
    {
        const int ny = NTOK * D_INNER / 4;
        cvt_f16x2_kernel<<<(ny + 255) / 256, 256>>>(y, yc, yc + (size_t)NTOK * D_INNER, ny);
    }

    // 5) out_proj: out[4096, 2048] = y * W2^T
    {
        dim3 grid(NTOK / 128, (D_MODEL + 255) / 256);
        mma_gemm_f16x3<<<grid, 512, GEMM_SMEM>>>(
            yc, yc + (size_t)NTOK * D_INNER,
            w2c, w2c + (size_t)D_MODEL * D_INNER,
            out, NTOK, D_MODEL, D_INNER);
    }
}

// round 6
// speedup vs baseline: 1.0193x; 1.0129x over previous
#include <cuda_runtime.h>
#include <cuda_fp16.h>
#include <math.h>
#include <stdint.h>

#define D_MODEL   2048
#define D_INNER   4096
#define D_STATE   128
#define HEADDIM   64
#define NHEADS    64
#define CONV_DIM  4352     /* D_INNER + 2*D_STATE */
#define D_IN_PROJ 8512     /* 2*D_INNER + 2*D_STATE + NHEADS */
#define BATCH     2
#define TLEN      2048
#define NTOK      (BATCH*TLEN)   /* 4096 */
#define RMS_EPS   1e-5f

// ---------------- scratch (device globals; no allocs allowed) ----------------
__device__ float g_zx [(size_t)NTOK * D_IN_PROJ];   // in_proj output
__device__ float g_xbc[(size_t)NTOK * CONV_DIM];    // conv+silu output
__device__ float g_y  [(size_t)NTOK * D_INNER];     // scan output

// fp16 hi/lo planes
__device__ __half g_xc [(size_t)2 * NTOK * D_MODEL];
__device__ __half g_w1c[(size_t)2 * D_IN_PROJ * D_MODEL];
__device__ __half g_yc [(size_t)2 * NTOK * D_INNER];
__device__ __half g_w2c[(size_t)2 * D_MODEL * D_INNER];

__device__ __forceinline__ uint32_t smem_to_u32(const void* p) {
    uint32_t a;
    asm("{ .reg .u64 t; cvta.to.shared.u64 t, %1; cvt.u32.u64 %0, t; }" : "=r"(a) : "l"(p));
    return a;
}

// ---------------- fp32 -> (hi, lo) fp16 planes ----------------
__global__ void __launch_bounds__(256) cvt_f16x2_kernel(
    const float* __restrict__ src, __half* __restrict__ hi, __half* __restrict__ lo, int n4)
{
    const int i = blockIdx.x * 256 + threadIdx.x;
    if (i >= n4) return;
    const float4 v = ((const float4*)src)[i];
    __half h0 = __float2half_rn(v.x), h1 = __float2half_rn(v.y);
    __half h2 = __float2half_rn(v.z), h3 = __float2half_rn(v.w);
    __half l0 = __float2half_rn(v.x - __half2float(h0));
    __half l1 = __float2half_rn(v.y - __half2float(h1));
    __half l2 = __float2half_rn(v.z - __half2float(h2));
    __half l3 = __float2half_rn(v.w - __half2float(h3));
    __half2* hp = (__half2*)(hi + (size_t)i * 4);
    __half2* lp = (__half2*)(lo + (size_t)i * 4);
    hp[0] = __halves2half2(h0, h1); hp[1] = __halves2half2(h2, h3);
    lp[0] = __halves2half2(l0, l1); lp[1] = __halves2half2(l2, l3);
}

// ======================= fp16x3 GEMM, 128x128 tile, 256 threads =======================
// acc += Ahi*Bhi + Ahi*Blo + Alo*Bhi  (fp32 accumulate), term-major MMA order,
// ldmatrix fragment loads, 3-stage cp.async pipeline, 1 syncthreads per chunk.

#define PADH 40
#define PLANE_H (128 * PADH)               /* 5120 halves per plane */
#define STAGE_B (4 * PLANE_H * 2)          /* Ahi Alo Bhi Blo = 40960 bytes */
#define GEMM_SMEM (3 * STAGE_B)            /* 122880 B */

__device__ __forceinline__ void mma16816(float* c, const uint32_t* a, const uint32_t* b) {
    asm volatile(
        "mma.sync.aligned.m16n8k16.row.col.f32.f16.f16.f32 "
        "{%0,%1,%2,%3}, {%4,%5,%6,%7}, {%8,%9}, {%0,%1,%2,%3};"
        : "+f"(c[0]), "+f"(c[1]), "+f"(c[2]), "+f"(c[3])
        : "r"(a[0]), "r"(a[1]), "r"(a[2]), "r"(a[3]), "r"(b[0]), "r"(b[1]));
}
__device__ __forceinline__ void ldsm4(uint32_t& r0, uint32_t& r1, uint32_t& r2, uint32_t& r3,
                                      uint32_t addr) {
    asm volatile("ldmatrix.sync.aligned.m8n8.x4.shared.b16 {%0,%1,%2,%3}, [%4];"
                 : "=r"(r0), "=r"(r1), "=r"(r2), "=r"(r3) : "r"(addr));
}

__global__ void __launch_bounds__(256, 1) mma_gemm_f16x3(
    const __half* __restrict__ Ahi, const __half* __restrict__ Alo,
    const __half* __restrict__ Bhi, const __half* __restrict__ Blo,
    float* __restrict__ C, int M, int N, int K)
{
    extern __shared__ __half sh[];
    const int tid  = threadIdx.x;
    const int wid  = tid >> 5;
    const int lane = tid & 31;
    const int g    = lane >> 2;
    const int tig  = lane & 3;
    const int bm   = blockIdx.x * 128;
    const int bn   = blockIdx.y * 128;
    const int wm   = (wid & 1) * 64;
    const int wn   = (wid >> 1) * 32;

    const uint32_t sbase = smem_to_u32(sh);

    // ldmatrix lane-derived offsets
    const int a_r = lane & 15;
    const int a_c = (lane >> 4) * 8;
    const int b_r = (lane & 7) + ((lane >> 4) << 3);
    const int b_c = ((lane >> 3) & 1) * 8;

    float acc[4][4][4];
#pragma unroll
    for (int mt = 0; mt < 4; ++mt)
#pragma unroll
        for (int nt = 0; nt < 4; ++nt)
#pragma unroll
            for (int q = 0; q < 4; ++q) acc[mt][nt][q] = 0.f;

    const int NC = K >> 5;   // BK = 32

    auto load_stage = [&](int s, int c) {
        const int kb = c * 32;
        const uint32_t stg = sbase + (uint32_t)s * STAGE_B;
        // 4 planes x 512 16B-chunks; 8 cp.async per thread
#pragma unroll
        for (int i = 0; i < 2; ++i) {
            const int f   = tid + 256 * i;       // 0..511
            const int row = f >> 2;              // 0..127
            const int seg = (f & 3) * 8;         // halves
            const uint32_t doff = (uint32_t)(row * PADH + seg) * 2u;
            // A hi / lo (rows always valid)
            {
                const __half* p  = Ahi + (size_t)(bm + row) * K + kb + seg;
                asm volatile("cp.async.cg.shared.global [%0], [%1], 16;"
                             :: "r"(stg + doff), "l"(p) : "memory");
                const __half* q2 = Alo + (size_t)(bm + row) * K + kb + seg;
                asm volatile("cp.async.cg.shared.global [%0], [%1], 16;"
                             :: "r"(stg + (uint32_t)PLANE_H * 2u + doff), "l"(q2) : "memory");
            }
            // B hi / lo (row guard with zero fill)
            {
                const int brow = bn + row;
                const int safe = (brow < N) ? brow : 0;
                const uint32_t sz = (brow < N) ? 16u : 0u;
                const __half* p  = Bhi + (size_t)safe * K + kb + seg;
                asm volatile("cp.async.cg.shared.global [%0], [%1], 16, %2;"
                             :: "r"(stg + (uint32_t)(2 * PLANE_H) * 2u + doff), "l"(p), "r"(sz) : "memory");
                const __half* q2 = Blo + (size_t)safe * K + kb + seg;
                asm volatile("cp.async.cg.shared.global [%0], [%1], 16, %2;"
                             :: "r"(stg + (uint32_t)(3 * PLANE_H) * 2u + doff), "l"(q2), "r"(sz) : "memory");
            }
        }
        asm volatile("cp.async.commit_group;" ::: "memory");
    };

    auto compute_stage = [&](int s) {
        const uint32_t stg  = sbase + (uint32_t)s * STAGE_B;
        const uint32_t aHi  = stg;
        const uint32_t aLo  = stg + (uint32_t)PLANE_H * 2u;
        const uint32_t bHi  = stg + (uint32_t)(2 * PLANE_H) * 2u;
        const uint32_t bLo  = stg + (uint32_t)(3 * PLANE_H) * 2u;
#pragma unroll
        for (int ks = 0; ks < 2; ++ks) {
            const int k0 = ks * 16;
            uint32_t ah[4][4], al[4][4], bh[4][2], bl[4][2];
            // B fragments: 2 ldmatrix.x4 per plane
#pragma unroll
            for (int p = 0; p < 2; ++p) {
                const uint32_t off = (uint32_t)((wn + p * 16 + b_r) * PADH + k0 + b_c) * 2u;
                ldsm4(bh[2*p][0], bh[2*p][1], bh[2*p+1][0], bh[2*p+1][1], bHi + off);
                ldsm4(bl[2*p][0], bl[2*p][1], bl[2*p+1][0], bl[2*p+1][1], bLo + off);
            }
            // A fragments: 1 ldmatrix.x4 per (mt, plane)
#pragma unroll
            for (int mt = 0; mt < 4; ++mt) {
                const uint32_t off = (uint32_t)((wm + mt * 16 + a_r) * PADH + k0 + a_c) * 2u;
                ldsm4(ah[mt][0], ah[mt][1], ah[mt][2], ah[mt][3], aHi + off);
                ldsm4(al[mt][0], al[mt][1], al[mt][2], al[mt][3], aLo + off);
            }
            // term-major MMA order: chain distance 16 on each accumulator
#pragma unroll
            for (int mt = 0; mt < 4; ++mt)
#pragma unroll
                for (int nt = 0; nt < 4; ++nt)
                    mma16816(acc[mt][nt], ah[mt], bh[nt]);
#pragma unroll
            for (int mt = 0; mt < 4; ++mt)
#pragma unroll
                for (int nt = 0; nt < 4; ++nt)
                    mma16816(acc[mt][nt], ah[mt], bl[nt]);
#pragma unroll
            for (int mt = 0; mt < 4; ++mt)
#pragma unroll
                for (int nt = 0; nt < 4; ++nt)
                    mma16816(acc[mt][nt], al[mt], bh[nt]);
        }
    };

    // 3-stage pipeline, one barrier per chunk
    load_stage(0, 0);
    load_stage(1, 1);
    for (int c = 0; c < NC; ++c) {
        asm volatile("cp.async.wait_group 1;" ::: "memory");
        __syncthreads();
        if (c + 2 < NC) load_stage((c + 2) % 3, c + 2);
        compute_stage(c % 3);
    }

#pragma unroll
    for (int mt = 0; mt < 4; ++mt) {
        const int row0 = bm + wm + mt * 16 + g;
#pragma unroll
        for (int nt = 0; nt < 4; ++nt) {
            const int col = bn + wn + nt * 8 + tig * 2;
            if (col < N) {
                *(float2*)(C + (size_t)row0 * N + col)       = make_float2(acc[mt][nt][0], acc[mt][nt][1]);
                *(float2*)(C + (size_t)(row0 + 8) * N + col) = make_float2(acc[mt][nt][2], acc[mt][nt][3]);
            }
        }
    }
}

// ---------------- depthwise causal conv (width 4) + SiLU ----------------
__global__ void __launch_bounds__(256) conv_silu_kernel(
    const float* __restrict__ cw, const float* __restrict__ cb)
{
    const int c  = blockIdx.x * 256 + threadIdx.x;
    const int b  = blockIdx.z;
    const int t0 = blockIdx.y * 32;

    const float w0 = cw[c*4+0], w1 = cw[c*4+1], w2 = cw[c*4+2], w3 = cw[c*4+3];
    const float bias = cb[c];

    const float* base = g_zx + ((size_t)b * TLEN) * D_IN_PROJ + D_INNER + c;
    float* ob = g_xbc + ((size_t)b * TLEN) * CONV_DIM + c;

    float x0 = (t0 >= 3) ? base[(size_t)(t0-3) * D_IN_PROJ] : 0.f;
    float x1 = (t0 >= 2) ? base[(size_t)(t0-2) * D_IN_PROJ] : 0.f;
    float x2 = (t0 >= 1) ? base[(size_t)(t0-1) * D_IN_PROJ] : 0.f;

    for (int t = t0; t < t0 + 32; ++t) {
        const float x3 = base[(size_t)t * D_IN_PROJ];
        const float v  = bias + x0*w0 + x1*w1 + x2*w2 + x3*w3;
        ob[(size_t)t * CONV_DIM] = v / (1.f + expf(-v));
        x0 = x1; x1 = x2; x2 = x3;
    }
}

// ---------------- SSM scan (256 threads: thread owns 32 states) ----------------
#define SCAN_TC 8
__global__ void __launch_bounds__(256) scan_kernel(
    const float* __restrict__ dt_bias, const float* __restrict__ A_log,
    const float* __restrict__ Dskip)
{
    const int h   = blockIdx.x;
    const int b   = blockIdx.y;
    const int tid = threadIdx.x;
    const int p   = tid >> 2;        // head-dim element 0..63
    const int q   = tid & 3;         // state quarter
    const int nb  = q * 32;

    __shared__ __align__(16) float sB[SCAN_TC][128];
    __shared__ __align__(16) float sC[SCAN_TC][128];
    __shared__ __align__(16) float sX[SCAN_TC][64];
    __shared__ float sDA[SCAN_TC], sDT[SCAN_TC];

    float4 hst[8];
#pragma unroll
    for (int r = 0; r < 8; ++r) hst[r] = make_float4(0.f,0.f,0.f,0.f);

    const float Acoef = -expf(A_log[h]);
    const float dtb   = dt_bias[h];
    const float dsk   = Dskip[h];

    const float* xbc_b    = g_xbc + (size_t)b * TLEN * CONV_DIM;
    const float* dtr_base = g_zx  + (size_t)b * TLEN * D_IN_PROJ + (D_INNER + CONV_DIM) + h;
    float*       y_base   = g_y   + (size_t)b * TLEN * D_INNER + h * HEADDIM;

    for (int t0 = 0; t0 < TLEN; t0 += SCAN_TC) {
        for (int i = tid; i < SCAN_TC * 128; i += 256) {
            const int tl = i >> 7, c = i & 127;
            const float* row = xbc_b + (size_t)(t0 + tl) * CONV_DIM + D_INNER;
            sB[tl][c] = row[c];
            sC[tl][c] = row[D_STATE + c];
        }
        for (int i = tid; i < SCAN_TC * 64; i += 256) {
            const int tl = i >> 6, c = i & 63;
            sX[tl][c] = xbc_b[(size_t)(t0 + tl) * CONV_DIM + h * HEADDIM + c];
        }
        if (tid < SCAN_TC) {
            const float raw = dtr_base[(size_t)(t0 + tid) * D_IN_PROJ] + dtb;
            const float dt  = (raw > 20.f) ? raw : log1pf(expf(raw));
            sDT[tid] = dt;
            sDA[tid] = expf(dt * Acoef);
        }
        __syncthreads();

#pragma unroll
        for (int tl = 0; tl < SCAN_TC; ++tl) {
            const float dA  = sDA[tl];
            const float dtx = sDT[tl] * sX[tl][p];
            const float4* B4 = (const float4*)&sB[tl][nb];
            const float4* C4 = (const float4*)&sC[tl][nb];
            float y = 0.f;
#pragma unroll
            for (int r = 0; r < 8; ++r) {
                const float4 bb = B4[r];
                const float4 cc = C4[r];
                hst[r].x = hst[r].x * dA + dtx * bb.x;  y += hst[r].x * cc.x;
                hst[r].y = hst[r].y * dA + dtx * bb.y;  y += hst[r].y * cc.y;
                hst[r].z = hst[r].z * dA + dtx * bb.z;  y += hst[r].z * cc.z;
                hst[r].w = hst[r].w * dA + dtx * bb.w;  y += hst[r].w * cc.w;
            }
            y += __shfl_xor_sync(0xffffffffu, y, 1);
            y += __shfl_xor_sync(0xffffffffu, y, 2);
            if (q == 0) {
                y += dsk * sX[tl][p];
                y_base[(size_t)(t0 + tl) * D_INNER + p] = y;
            }
        }
        __syncthreads();
    }
}

// ---------------- gate + RMSNorm, emits fp16 hi/lo planes directly ----------------
__global__ void __launch_bounds__(256) gate_norm_cvt_kernel(
    const float* __restrict__ nw, __half* __restrict__ yhi, __half* __restrict__ ylo)
{
    const int row = blockIdx.x;
    const int tid = threadIdx.x;
    const float* zrow = g_zx + (size_t)row * D_IN_PROJ;
    const float* yrow = g_y  + (size_t)row * D_INNER;

    float g[16];
    float ss = 0.f;
#pragma unroll
    for (int i = 0; i < 4; ++i) {
        const int e = i * 1024 + tid * 4;
        const float4 yv = *(const float4*)(yrow + e);
        const float4 zv = *(const float4*)(zrow + e);
        float g0 = yv.x * (zv.x / (1.f + expf(-zv.x)));
        float g1 = yv.y * (zv.y / (1.f + expf(-zv.y)));
        float g2 = yv.z * (zv.z / (1.f + expf(-zv.z)));
        float g3 = yv.w * (zv.w / (1.f + expf(-zv.w)));
        g[i*4+0] = g0; g[i*4+1] = g1; g[i*4+2] = g2; g[i*4+3] = g3;
        ss += g0*g0 + g1*g1 + g2*g2 + g3*g3;
    }

    ss += __shfl_xor_sync(0xffffffffu, ss, 16);
    ss += __shfl_xor_sync(0xffffffffu, ss, 8);
    ss += __shfl_xor_sync(0xffffffffu, ss, 4);
    ss += __shfl_xor_sync(0xffffffffu, ss, 2);
    ss += __shfl_xor_sync(0xffffffffu, ss, 1);
    __shared__ float red[8];
    if ((tid & 31) == 0) red[tid >> 5] = ss;
    __syncthreads();
    float tot = 0.f;
#pragma unroll
    for (int w = 0; w < 8; ++w) tot += red[w];

    const float scale = rsqrtf(tot / (float)D_INNER + RMS_EPS);
#pragma unroll
    for (int i = 0; i < 4; ++i) {
        const int e = i * 1024 + tid * 4;
        __half2 hv[2], lv[2];
#pragma unroll
        for (int j = 0; j < 2; ++j) {
            const float v0 = g[i*4 + j*2 + 0] * scale * nw[e + j*2 + 0];
            const float v1 = g[i*4 + j*2 + 1] * scale * nw[e + j*2 + 1];
            const __half h0 = __float2half_rn(v0), h1 = __float2half_rn(v1);
            hv[j] = __halves2half2(h0, h1);
            lv[j] = __halves2half2(__float2half_rn(v0 - __half2float(h0)),
                                   __float2half_rn(v1 - __half2float(h1)));
        }
        *(__half2*)(yhi + (size_t)row * D_INNER + e)     = hv[0];
        *(__half2*)(yhi + (size_t)row * D_INNER + e + 2) = hv[1];
        *(__half2*)(ylo + (size_t)row * D_INNER + e)     = lv[0];
        *(__half2*)(ylo + (size_t)row * D_INNER + e + 2) = lv[1];
    }
}

// ---------------- launch ----------------
extern "C" void kernel_launch(void* const* d_in, const int* in_sizes, int n_in,
                              void* d_out, int out_size)
{
    const float* x          = (const float*)d_in[0];
    const float* in_proj_w  = (const float*)d_in[3];
    const float* conv_w     = (const float*)d_in[4];
    const float* conv_b     = (const float*)d_in[5];
    const float* dt_bias    = (const float*)d_in[6];
    const float* A_log      = (const float*)d_in[7];
    const float* Dskip      = (const float*)d_in[8];
    const float* norm_w     = (const float*)d_in[9];
    const float* out_proj_w = (const float*)d_in[10];
    float* out = (float*)d_out;

    float *zx;
    __half *xc, *w1c, *yc, *w2c;
    cudaGetSymbolAddress((void**)&zx,  g_zx);
    cudaGetSymbolAddress((void**)&xc,  g_xc);
    cudaGetSymbolAddress((void**)&w1c, g_w1c);
    cudaGetSymbolAddress((void**)&yc,  g_yc);
    cudaGetSymbolAddress((void**)&w2c, g_w2c);

    cudaFuncSetAttribute(mma_gemm_f16x3,
                         cudaFuncAttributeMaxDynamicSharedMemorySize, GEMM_SMEM);

    // 0) convert x and weights to fp16 hi/lo planes
    {
        const int nx = NTOK * D_MODEL / 4;
        cvt_f16x2_kernel<<<(nx + 255) / 256, 256>>>(x, xc, xc + (size_t)NTOK * D_MODEL, nx);
        const int nw1 = D_IN_PROJ * D_MODEL / 4;
        cvt_f16x2_kernel<<<(nw1 + 255) / 256, 256>>>(in_proj_w, w1c, w1c + (size_t)D_IN_PROJ * D_MODEL, nw1);
        const int nw2 = D_MODEL * D_INNER / 4;
        cvt_f16x2_kernel<<<(nw2 + 255) / 256, 256>>>(out_proj_w, w2c, w2c + (size_t)D_MODEL * D_INNER, nw2);
    }

    // 1) in_proj
    {
        dim3 grid(NTOK / 128, (D_IN_PROJ + 127) / 128);
        mma_gemm_f16x3<<<grid, 256, GEMM_SMEM>>>(
            xc, xc + (size_t)NTOK * D_MODEL,
            w1c, w1c + (size_t)D_IN_PROJ * D_MODEL,
            zx, NTOK, D_IN_PROJ, D_MODEL);
    }
    // 2) conv + silu
    {
        dim3 grid(CONV_DIM / 256, TLEN / 32, BATCH);
        conv_silu_kernel<<<grid, 256>>>(conv_w, conv_b);
    }
    // 3) SSM scan
    {
        dim3 grid(NHEADS, BATCH);
        scan_kernel<<<grid, 256>>>(dt_bias, A_log, Dskip);
    }
    // 4) gate + RMSNorm + fp16 split (fused)
    gate_norm_cvt_kernel<<<NTOK, 256>>>(norm_w, yc, yc + (size_t)NTOK * D_INNER);

    // 5) out_proj
    {
        dim3 grid(NTOK / 128, D_MODEL / 128);
        mma_gemm_f16x3<<<grid, 256, GEMM_SMEM>>>(
            yc, yc + (size_t)NTOK * D_INNER,
            w2c, w2c + (size_t)D_MODEL * D_INNER,
            out, NTOK, D_MODEL, D_INNER);
    }
}

// round 7
// speedup vs baseline: 1.1387x; 1.1171x over previous
#include <cuda_runtime.h>
#include <cuda_fp16.h>
#include <math.h>
#include <stdint.h>

#define D_MODEL   2048
#define D_INNER   4096
#define D_STATE   128
#define HEADDIM   64
#define NHEADS    64
#define CONV_DIM  4352     /* D_INNER + 2*D_STATE */
#define D_IN_PROJ 8512     /* 2*D_INNER + 2*D_STATE + NHEADS */
#define BATCH     2
#define TLEN      2048
#define NTOK      (BATCH*TLEN)   /* 4096 */
#define RMS_EPS   1e-5f

// ---------------- scratch (device globals; no allocs allowed) ----------------
__device__ float g_zx [(size_t)NTOK * D_IN_PROJ];   // in_proj output
__device__ float g_xbc[(size_t)NTOK * CONV_DIM];    // conv+silu output
__device__ float g_y  [(size_t)NTOK * D_INNER];     // scan output

// fp16 planes: activations hi-only; weights hi+lo
__device__ __half g_xc [(size_t)NTOK * D_MODEL];
__device__ __half g_w1c[(size_t)2 * D_IN_PROJ * D_MODEL];
__device__ __half g_yc [(size_t)NTOK * D_INNER];
__device__ __half g_w2c[(size_t)2 * D_MODEL * D_INNER];

__device__ __forceinline__ uint32_t smem_to_u32(const void* p) {
    uint32_t a;
    asm("{ .reg .u64 t; cvta.to.shared.u64 t, %1; cvt.u32.u64 %0, t; }" : "=r"(a) : "l"(p));
    return a;
}

// ---------------- fp32 -> fp16 hi plane only ----------------
__global__ void __launch_bounds__(256) cvt_hi_kernel(
    const float* __restrict__ src, __half* __restrict__ hi, int n4)
{
    const int i = blockIdx.x * 256 + threadIdx.x;
    if (i >= n4) return;
    const float4 v = ((const float4*)src)[i];
    __half2* hp = (__half2*)(hi + (size_t)i * 4);
    hp[0] = __halves2half2(__float2half_rn(v.x), __float2half_rn(v.y));
    hp[1] = __halves2half2(__float2half_rn(v.z), __float2half_rn(v.w));
}

// ---------------- fp32 -> (hi, lo) fp16 planes (weights) ----------------
__global__ void __launch_bounds__(256) cvt_f16x2_kernel(
    const float* __restrict__ src, __half* __restrict__ hi, __half* __restrict__ lo, int n4)
{
    const int i = blockIdx.x * 256 + threadIdx.x;
    if (i >= n4) return;
    const float4 v = ((const float4*)src)[i];
    __half h0 = __float2half_rn(v.x), h1 = __float2half_rn(v.y);
    __half h2 = __float2half_rn(v.z), h3 = __float2half_rn(v.w);
    __half l0 = __float2half_rn(v.x - __half2float(h0));
    __half l1 = __float2half_rn(v.y - __half2float(h1));
    __half l2 = __float2half_rn(v.z - __half2float(h2));
    __half l3 = __float2half_rn(v.w - __half2float(h3));
    __half2* hp = (__half2*)(hi + (size_t)i * 4);
    __half2* lp = (__half2*)(lo + (size_t)i * 4);
    hp[0] = __halves2half2(h0, h1); hp[1] = __halves2half2(h2, h3);
    lp[0] = __halves2half2(l0, l1); lp[1] = __halves2half2(l2, l3);
}

// ======================= fp16x2 GEMM, 128x128 tile, 256 threads =======================
// C[M,N] = A[M,K] * B[N,K]^T ; acc += Ahi*Bhi + Ahi*Blo  (B covered to ~22 bits,
// dropped Alo*B term ~2^-11 relative). Term-major MMA order, ldmatrix loads,
// 3-stage cp.async pipeline, one syncthreads per chunk.

#define PADH 40
#define PLANE_H (128 * PADH)               /* 5120 halves per plane */
#define STAGE_B (3 * PLANE_H * 2)          /* Ahi Bhi Blo = 30720 bytes */
#define GEMM_SMEM (3 * STAGE_B)            /* 92160 B */

__device__ __forceinline__ void mma16816(float* c, const uint32_t* a, const uint32_t* b) {
    asm volatile(
        "mma.sync.aligned.m16n8k16.row.col.f32.f16.f16.f32 "
        "{%0,%1,%2,%3}, {%4,%5,%6,%7}, {%8,%9}, {%0,%1,%2,%3};"
        : "+f"(c[0]), "+f"(c[1]), "+f"(c[2]), "+f"(c[3])
        : "r"(a[0]), "r"(a[1]), "r"(a[2]), "r"(a[3]), "r"(b[0]), "r"(b[1]));
}
__device__ __forceinline__ void ldsm4(uint32_t& r0, uint32_t& r1, uint32_t& r2, uint32_t& r3,
                                      uint32_t addr) {
    asm volatile("ldmatrix.sync.aligned.m8n8.x4.shared.b16 {%0,%1,%2,%3}, [%4];"
                 : "=r"(r0), "=r"(r1), "=r"(r2), "=r"(r3) : "r"(addr));
}

__global__ void __launch_bounds__(256, 1) mma_gemm_f16x2(
    const __half* __restrict__ Ahi,
    const __half* __restrict__ Bhi, const __half* __restrict__ Blo,
    float* __restrict__ C, int M, int N, int K)
{
    extern __shared__ __half sh[];
    const int tid  = threadIdx.x;
    const int wid  = tid >> 5;
    const int lane = tid & 31;
    const int g    = lane >> 2;
    const int tig  = lane & 3;
    const int bm   = blockIdx.x * 128;
    const int bn   = blockIdx.y * 128;
    const int wm   = (wid & 1) * 64;
    const int wn   = (wid >> 1) * 32;

    const uint32_t sbase = smem_to_u32(sh);

    const int a_r = lane & 15;
    const int a_c = (lane >> 4) * 8;
    const int b_r = (lane & 7) + ((lane >> 4) << 3);
    const int b_c = ((lane >> 3) & 1) * 8;

    float acc[4][4][4];
#pragma unroll
    for (int mt = 0; mt < 4; ++mt)
#pragma unroll
        for (int nt = 0; nt < 4; ++nt)
#pragma unroll
            for (int q = 0; q < 4; ++q) acc[mt][nt][q] = 0.f;

    const int NC = K >> 5;   // BK = 32

    auto load_stage = [&](int s, int c) {
        const int kb = c * 32;
        const uint32_t stg = sbase + (uint32_t)s * STAGE_B;
        // 3 planes x 512 16B-chunks; 6 cp.async per thread
#pragma unroll
        for (int i = 0; i < 2; ++i) {
            const int f   = tid + 256 * i;       // 0..511
            const int row = f >> 2;              // 0..127
            const int seg = (f & 3) * 8;         // halves
            const uint32_t doff = (uint32_t)(row * PADH + seg) * 2u;
            // A hi (rows always valid)
            {
                const __half* p = Ahi + (size_t)(bm + row) * K + kb + seg;
                asm volatile("cp.async.cg.shared.global [%0], [%1], 16;"
                             :: "r"(stg + doff), "l"(p) : "memory");
            }
            // B hi / lo (row guard with zero fill)
            {
                const int brow = bn + row;
                const int safe = (brow < N) ? brow : 0;
                const uint32_t sz = (brow < N) ? 16u : 0u;
                const __half* p  = Bhi + (size_t)safe * K + kb + seg;
                asm volatile("cp.async.cg.shared.global [%0], [%1], 16, %2;"
                             :: "r"(stg + (uint32_t)PLANE_H * 2u + doff), "l"(p), "r"(sz) : "memory");
                const __half* q2 = Blo + (size_t)safe * K + kb + seg;
                asm volatile("cp.async.cg.shared.global [%0], [%1], 16, %2;"
                             :: "r"(stg + (uint32_t)(2 * PLANE_H) * 2u + doff), "l"(q2), "r"(sz) : "memory");
            }
        }
        asm volatile("cp.async.commit_group;" ::: "memory");
    };

    auto compute_stage = [&](int s) {
        const uint32_t stg = sbase + (uint32_t)s * STAGE_B;
        const uint32_t aHi = stg;
        const uint32_t bHi = stg + (uint32_t)PLANE_H * 2u;
        const uint32_t bLo = stg + (uint32_t)(2 * PLANE_H) * 2u;
#pragma unroll
        for (int ks = 0; ks < 2; ++ks) {
            const int k0 = ks * 16;
            uint32_t ah[4][4], bh[4][2], bl[4][2];
#pragma unroll
            for (int p = 0; p < 2; ++p) {
                const uint32_t off = (uint32_t)((wn + p * 16 + b_r) * PADH + k0 + b_c) * 2u;
                ldsm4(bh[2*p][0], bh[2*p][1], bh[2*p+1][0], bh[2*p+1][1], bHi + off);
                ldsm4(bl[2*p][0], bl[2*p][1], bl[2*p+1][0], bl[2*p+1][1], bLo + off);
            }
#pragma unroll
            for (int mt = 0; mt < 4; ++mt) {
                const uint32_t off = (uint32_t)((wm + mt * 16 + a_r) * PADH + k0 + a_c) * 2u;
                ldsm4(ah[mt][0], ah[mt][1], ah[mt][2], ah[mt][3], aHi + off);
            }
            // term-major: chain distance 16 per accumulator
#pragma unroll
            for (int mt = 0; mt < 4; ++mt)
#pragma unroll
                for (int nt = 0; nt < 4; ++nt)
                    mma16816(acc[mt][nt], ah[mt], bh[nt]);
#pragma unroll
            for (int mt = 0; mt < 4; ++mt)
#pragma unroll
                for (int nt = 0; nt < 4; ++nt)
                    mma16816(acc[mt][nt], ah[mt], bl[nt]);
        }
    };

    load_stage(0, 0);
    load_stage(1, 1);
    for (int c = 0; c < NC; ++c) {
        asm volatile("cp.async.wait_group 1;" ::: "memory");
        __syncthreads();
        if (c + 2 < NC) load_stage((c + 2) % 3, c + 2);
        compute_stage(c % 3);
    }

#pragma unroll
    for (int mt = 0; mt < 4; ++mt) {
        const int row0 = bm + wm + mt * 16 + g;
#pragma unroll
        for (int nt = 0; nt < 4; ++nt) {
            const int col = bn + wn + nt * 8 + tig * 2;
            if (col < N) {
                *(float2*)(C + (size_t)row0 * N + col)       = make_float2(acc[mt][nt][0], acc[mt][nt][1]);
                *(float2*)(C + (size_t)(row0 + 8) * N + col) = make_float2(acc[mt][nt][2], acc[mt][nt][3]);
            }
        }
    }
}

// ---------------- depthwise causal conv (width 4) + SiLU ----------------
__global__ void __launch_bounds__(256) conv_silu_kernel(
    const float* __restrict__ cw, const float* __restrict__ cb)
{
    const int c  = blockIdx.x * 256 + threadIdx.x;
    const int b  = blockIdx.z;
    const int t0 = blockIdx.y * 32;

    const float w0 = cw[c*4+0], w1 = cw[c*4+1], w2 = cw[c*4+2], w3 = cw[c*4+3];
    const float bias = cb[c];

    const float* base = g_zx + ((size_t)b * TLEN) * D_IN_PROJ + D_INNER + c;
    float* ob = g_xbc + ((size_t)b * TLEN) * CONV_DIM + c;

    float x0 = (t0 >= 3) ? base[(size_t)(t0-3) * D_IN_PROJ] : 0.f;
    float x1 = (t0 >= 2) ? base[(size_t)(t0-2) * D_IN_PROJ] : 0.f;
    float x2 = (t0 >= 1) ? base[(size_t)(t0-1) * D_IN_PROJ] : 0.f;

    for (int t = t0; t < t0 + 32; ++t) {
        const float x3 = base[(size_t)t * D_IN_PROJ];
        const float v  = bias + x0*w0 + x1*w1 + x2*w2 + x3*w3;
        ob[(size_t)t * CONV_DIM] = v / (1.f + expf(-v));
        x0 = x1; x1 = x2; x2 = x3;
    }
}

// ---------------- SSM scan (256 threads: thread owns 32 states) ----------------
#define SCAN_TC 8
__global__ void __launch_bounds__(256) scan_kernel(
    const float* __restrict__ dt_bias, const float* __restrict__ A_log,
    const float* __restrict__ Dskip)
{
    const int h   = blockIdx.x;
    const int b   = blockIdx.y;
    const int tid = threadIdx.x;
    const int p   = tid >> 2;
    const int q   = tid & 3;
    const int nb  = q * 32;

    __shared__ __align__(16) float sB[SCAN_TC][128];
    __shared__ __align__(16) float sC[SCAN_TC][128];
    __shared__ __align__(16) float sX[SCAN_TC][64];
    __shared__ float sDA[SCAN_TC], sDT[SCAN_TC];

    float4 hst[8];
#pragma unroll
    for (int r = 0; r < 8; ++r) hst[r] = make_float4(0.f,0.f,0.f,0.f);

    const float Acoef = -expf(A_log[h]);
    const float dtb   = dt_bias[h];
    const float dsk   = Dskip[h];

    const float* xbc_b    = g_xbc + (size_t)b * TLEN * CONV_DIM;
    const float* dtr_base = g_zx  + (size_t)b * TLEN * D_IN_PROJ + (D_INNER + CONV_DIM) + h;
    float*       y_base   = g_y   + (size_t)b * TLEN * D_INNER + h * HEADDIM;

    for (int t0 = 0; t0 < TLEN; t0 += SCAN_TC) {
        for (int i = tid; i < SCAN_TC * 128; i += 256) {
            const int tl = i >> 7, c = i & 127;
            const float* row = xbc_b + (size_t)(t0 + tl) * CONV_DIM + D_INNER;
            sB[tl][c] = row[c];
            sC[tl][c] = row[D_STATE + c];
        }
        for (int i = tid; i < SCAN_TC * 64; i += 256) {
            const int tl = i >> 6, c = i & 63;
            sX[tl][c] = xbc_b[(size_t)(t0 + tl) * CONV_DIM + h * HEADDIM + c];
        }
        if (tid < SCAN_TC) {
            const float raw = dtr_base[(size_t)(t0 + tid) * D_IN_PROJ] + dtb;
            const float dt  = (raw > 20.f) ? raw : log1pf(expf(raw));
            sDT[tid] = dt;
            sDA[tid] = expf(dt * Acoef);
        }
        __syncthreads();

#pragma unroll
        for (int tl = 0; tl < SCAN_TC; ++tl) {
            const float dA  = sDA[tl];
            const float dtx = sDT[tl] * sX[tl][p];
            const float4* B4 = (const float4*)&sB[tl][nb];
            const float4* C4 = (const float4*)&sC[tl][nb];
            float y = 0.f;
#pragma unroll
            for (int r = 0; r < 8; ++r) {
                const float4 bb = B4[r];
                const float4 cc = C4[r];
                hst[r].x = hst[r].x * dA + dtx * bb.x;  y += hst[r].x * cc.x;
                hst[r].y = hst[r].y * dA + dtx * bb.y;  y += hst[r].y * cc.y;
                hst[r].z = hst[r].z * dA + dtx * bb.z;  y += hst[r].z * cc.z;
                hst[r].w = hst[r].w * dA + dtx * bb.w;  y += hst[r].w * cc.w;
            }
            y += __shfl_xor_sync(0xffffffffu, y, 1);
            y += __shfl_xor_sync(0xffffffffu, y, 2);
            if (q == 0) {
                y += dsk * sX[tl][p];
                y_base[(size_t)(t0 + tl) * D_INNER + p] = y;
            }
        }
        __syncthreads();
    }
}

// ---------------- gate + RMSNorm, emits fp16 hi plane directly ----------------
__global__ void __launch_bounds__(256) gate_norm_cvt_kernel(
    const float* __restrict__ nw, __half* __restrict__ yhi)
{
    const int row = blockIdx.x;
    const int tid = threadIdx.x;
    const float* zrow = g_zx + (size_t)row * D_IN_PROJ;
    const float* yrow = g_y  + (size_t)row * D_INNER;

    float g[16];
    float ss = 0.f;
#pragma unroll
    for (int i = 0; i < 4; ++i) {
        const int e = i * 1024 + tid * 4;
        const float4 yv = *(const float4*)(yrow + e);
        const float4 zv = *(const float4*)(zrow + e);
        float g0 = yv.x * (zv.x / (1.f + expf(-zv.x)));
        float g1 = yv.y * (zv.y / (1.f + expf(-zv.y)));
        float g2 = yv.z * (zv.z / (1.f + expf(-zv.z)));
        float g3 = yv.w * (zv.w / (1.f + expf(-zv.w)));
        g[i*4+0] = g0; g[i*4+1] = g1; g[i*4+2] = g2; g[i*4+3] = g3;
        ss += g0*g0 + g1*g1 + g2*g2 + g3*g3;
    }

    ss += __shfl_xor_sync(0xffffffffu, ss, 16);
    ss += __shfl_xor_sync(0xffffffffu, ss, 8);
    ss += __shfl_xor_sync(0xffffffffu, ss, 4);
    ss += __shfl_xor_sync(0xffffffffu, ss, 2);
    ss += __shfl_xor_sync(0xffffffffu, ss, 1);
    __shared__ float red[8];
    if ((tid & 31) == 0) red[tid >> 5] = ss;
    __syncthreads();
    float tot = 0.f;
#pragma unroll
    for (int w = 0; w < 8; ++w) tot += red[w];

    const float scale = rsqrtf(tot / (float)D_INNER + RMS_EPS);
#pragma unroll
    for (int i = 0; i < 4; ++i) {
        const int e = i * 1024 + tid * 4;
        const float v0 = g[i*4+0] * scale * nw[e+0];
        const float v1 = g[i*4+1] * scale * nw[e+1];
        const float v2 = g[i*4+2] * scale * nw[e+2];
        const float v3 = g[i*4+3] * scale * nw[e+3];
        __half2* hp = (__half2*)(yhi + (size_t)row * D_INNER + e);
        hp[0] = __halves2half2(__float2half_rn(v0), __float2half_rn(v1));
        hp[1] = __halves2half2(__float2half_rn(v2), __float2half_rn(v3));
    }
}

// ---------------- launch ----------------
extern "C" void kernel_launch(void* const* d_in, const int* in_sizes, int n_in,
                              void* d_out, int out_size)
{
    const float* x          = (const float*)d_in[0];
    const float* in_proj_w  = (const float*)d_in[3];
    const float* conv_w     = (const float*)d_in[4];
    const float* conv_b     = (const float*)d_in[5];
    const float* dt_bias    = (const float*)d_in[6];
    const float* A_log      = (const float*)d_in[7];
    const float* Dskip      = (const float*)d_in[8];
    const float* norm_w     = (const float*)d_in[9];
    const float* out_proj_w = (const float*)d_in[10];
    float* out = (float*)d_out;

    float *zx;
    __half *xc, *w1c, *yc, *w2c;
    cudaGetSymbolAddress((void**)&zx,  g_zx);
    cudaGetSymbolAddress((void**)&xc,  g_xc);
    cudaGetSymbolAddress((void**)&w1c, g_w1c);
    cudaGetSymbolAddress((void**)&yc,  g_yc);
    cudaGetSymbolAddress((void**)&w2c, g_w2c);

    cudaFuncSetAttribute(mma_gemm_f16x2,
                         cudaFuncAttributeMaxDynamicSharedMemorySize, GEMM_SMEM);

    // 0) convert: x -> hi plane; weights -> hi+lo planes
    {
        const int nx = NTOK * D_MODEL / 4;
        cvt_hi_kernel<<<(nx + 255) / 256, 256>>>(x, xc, nx);
        const int nw1 = D_IN_PROJ * D_MODEL / 4;
        cvt_f16x2_kernel<<<(nw1 + 255) / 256, 256>>>(in_proj_w, w1c, w1c + (size_t)D_IN_PROJ * D_MODEL, nw1);
        const int nw2 = D_MODEL * D_INNER / 4;
        cvt_f16x2_kernel<<<(nw2 + 255) / 256, 256>>>(out_proj_w, w2c, w2c + (size_t)D_MODEL * D_INNER, nw2);
    }

    // 1) in_proj: zx[4096, 8512] = x * W1^T
    {
        dim3 grid(NTOK / 128, (D_IN_PROJ + 127) / 128);
        mma_gemm_f16x2<<<grid, 256, GEMM_SMEM>>>(
            xc,
            w1c, w1c + (size_t)D_IN_PROJ * D_MODEL,
            zx, NTOK, D_IN_PROJ, D_MODEL);
    }
    // 2) conv + silu
    {
        dim3 grid(CONV_DIM / 256, TLEN / 32, BATCH);
        conv_silu_kernel<<<grid, 256>>>(conv_w, conv_b);
    }
    // 3) SSM scan
    {
        dim3 grid(NHEADS, BATCH);
        scan_kernel<<<grid, 256>>>(dt_bias, A_log, Dskip);
    }
    // 4) gate + RMSNorm + fp16 hi (fused)
    gate_norm_cvt_kernel<<<NTOK, 256>>>(norm_w, yc);

    // 5) out_proj: out[4096, 2048] = y * W2^T
    {
        dim3 grid(NTOK / 128, D_MODEL / 128);
        mma_gemm_f16x2<<<grid, 256, GEMM_SMEM>>>(
            yc,
            w2c, w2c + (size_t)D_MODEL * D_INNER,
            out, NTOK, D_MODEL, D_INNER);
    }
}

// round 8
// speedup vs baseline: 1.6918x; 1.4857x over previous
#include <cuda_runtime.h>
#include <cuda_fp16.h>
#include <math.h>
#include <stdint.h>

#define D_MODEL   2048
#define D_INNER   4096
#define D_STATE   128
#define HEADDIM   64
#define NHEADS    64
#define CONV_DIM  4352     /* D_INNER + 2*D_STATE */
#define D_IN_PROJ 8512     /* 2*D_INNER + 2*D_STATE + NHEADS */
#define BATCH     2
#define TLEN      2048
#define NTOK      (BATCH*TLEN)   /* 4096 */
#define RMS_EPS   1e-5f

// ---------------- scratch (device globals; no allocs allowed) ----------------
__device__ float g_zx [(size_t)NTOK * D_IN_PROJ];   // in_proj output
__device__ float g_xbc[(size_t)NTOK * CONV_DIM];    // conv+silu output
__device__ float g_y  [(size_t)NTOK * D_INNER];     // scan output

// fp16 planes: activations hi-only; weights hi+lo
__device__ __half g_xc [(size_t)NTOK * D_MODEL];
__device__ __half g_w1c[(size_t)2 * D_IN_PROJ * D_MODEL];
__device__ __half g_yc [(size_t)NTOK * D_INNER];
__device__ __half g_w2c[(size_t)2 * D_MODEL * D_INNER];

__device__ __forceinline__ uint32_t smem_to_u32(const void* p) {
    uint32_t a;
    asm("{ .reg .u64 t; cvta.to.shared.u64 t, %1; cvt.u32.u64 %0, t; }" : "=r"(a) : "l"(p));
    return a;
}

// ---------------- fp32 -> fp16 hi plane only ----------------
__global__ void __launch_bounds__(256) cvt_hi_kernel(
    const float* __restrict__ src, __half* __restrict__ hi, int n4)
{
    const int i = blockIdx.x * 256 + threadIdx.x;
    if (i >= n4) return;
    const float4 v = ((const float4*)src)[i];
    __half2* hp = (__half2*)(hi + (size_t)i * 4);
    hp[0] = __halves2half2(__float2half_rn(v.x), __float2half_rn(v.y));
    hp[1] = __halves2half2(__float2half_rn(v.z), __float2half_rn(v.w));
}

// ---------------- fp32 -> (hi, lo) fp16 planes (weights) ----------------
__global__ void __launch_bounds__(256) cvt_f16x2_kernel(
    const float* __restrict__ src, __half* __restrict__ hi, __half* __restrict__ lo, int n4)
{
    const int i = blockIdx.x * 256 + threadIdx.x;
    if (i >= n4) return;
    const float4 v = ((const float4*)src)[i];
    __half h0 = __float2half_rn(v.x), h1 = __float2half_rn(v.y);
    __half h2 = __float2half_rn(v.z), h3 = __float2half_rn(v.w);
    __half l0 = __float2half_rn(v.x - __half2float(h0));
    __half l1 = __float2half_rn(v.y - __half2float(h1));
    __half l2 = __float2half_rn(v.z - __half2float(h2));
    __half l3 = __float2half_rn(v.w - __half2float(h3));
    __half2* hp = (__half2*)(hi + (size_t)i * 4);
    __half2* lp = (__half2*)(lo + (size_t)i * 4);
    hp[0] = __halves2half2(h0, h1); hp[1] = __halves2half2(h2, h3);
    lp[0] = __halves2half2(l0, l1); lp[1] = __halves2half2(l2, l3);
}

// ======================= fp16x2 GEMM, 128x128 tile, 256 threads =======================
// C[M,N] = A[M,K] * B[N,K]^T ; acc += Ahi*Bhi + Ahi*Blo.
// At the mma.sync HW instruction-rate ceiling (~16 cyc/SMSP/instr) — keep as-is.

#define PADH 40
#define PLANE_H (128 * PADH)               /* 5120 halves per plane */
#define STAGE_B (3 * PLANE_H * 2)          /* Ahi Bhi Blo = 30720 bytes */
#define GEMM_SMEM (3 * STAGE_B)            /* 92160 B */

__device__ __forceinline__ void mma16816(float* c, const uint32_t* a, const uint32_t* b) {
    asm volatile(
        "mma.sync.aligned.m16n8k16.row.col.f32.f16.f16.f32 "
        "{%0,%1,%2,%3}, {%4,%5,%6,%7}, {%8,%9}, {%0,%1,%2,%3};"
        : "+f"(c[0]), "+f"(c[1]), "+f"(c[2]), "+f"(c[3])
        : "r"(a[0]), "r"(a[1]), "r"(a[2]), "r"(a[3]), "r"(b[0]), "r"(b[1]));
}
__device__ __forceinline__ void ldsm4(uint32_t& r0, uint32_t& r1, uint32_t& r2, uint32_t& r3,
                                      uint32_t addr) {
    asm volatile("ldmatrix.sync.aligned.m8n8.x4.shared.b16 {%0,%1,%2,%3}, [%4];"
                 : "=r"(r0), "=r"(r1), "=r"(r2), "=r"(r3) : "r"(addr));
}

__global__ void __launch_bounds__(256, 1) mma_gemm_f16x2(
    const __half* __restrict__ Ahi,
    const __half* __restrict__ Bhi, const __half* __restrict__ Blo,
    float* __restrict__ C, int M, int N, int K)
{
    extern __shared__ __half sh[];
    const int tid  = threadIdx.x;
    const int wid  = tid >> 5;
    const int lane = tid & 31;
    const int g    = lane >> 2;
    const int tig  = lane & 3;
    const int bm   = blockIdx.x * 128;
    const int bn   = blockIdx.y * 128;
    const int wm   = (wid & 1) * 64;
    const int wn   = (wid >> 1) * 32;

    const uint32_t sbase = smem_to_u32(sh);

    const int a_r = lane & 15;
    const int a_c = (lane >> 4) * 8;
    const int b_r = (lane & 7) + ((lane >> 4) << 3);
    const int b_c = ((lane >> 3) & 1) * 8;

    float acc[4][4][4];
#pragma unroll
    for (int mt = 0; mt < 4; ++mt)
#pragma unroll
        for (int nt = 0; nt < 4; ++nt)
#pragma unroll
            for (int q = 0; q < 4; ++q) acc[mt][nt][q] = 0.f;

    const int NC = K >> 5;   // BK = 32

    auto load_stage = [&](int s, int c) {
        const int kb = c * 32;
        const uint32_t stg = sbase + (uint32_t)s * STAGE_B;
#pragma unroll
        for (int i = 0; i < 2; ++i) {
            const int f   = tid + 256 * i;       // 0..511
            const int row = f >> 2;              // 0..127
            const int seg = (f & 3) * 8;         // halves
            const uint32_t doff = (uint32_t)(row * PADH + seg) * 2u;
            {
                const __half* p = Ahi + (size_t)(bm + row) * K + kb + seg;
                asm volatile("cp.async.cg.shared.global [%0], [%1], 16;"
                             :: "r"(stg + doff), "l"(p) : "memory");
            }
            {
                const int brow = bn + row;
                const int safe = (brow < N) ? brow : 0;
                const uint32_t sz = (brow < N) ? 16u : 0u;
                const __half* p  = Bhi + (size_t)safe * K + kb + seg;
                asm volatile("cp.async.cg.shared.global [%0], [%1], 16, %2;"
                             :: "r"(stg + (uint32_t)PLANE_H * 2u + doff), "l"(p), "r"(sz) : "memory");
                const __half* q2 = Blo + (size_t)safe * K + kb + seg;
                asm volatile("cp.async.cg.shared.global [%0], [%1], 16, %2;"
                             :: "r"(stg + (uint32_t)(2 * PLANE_H) * 2u + doff), "l"(q2), "r"(sz) : "memory");
            }
        }
        asm volatile("cp.async.commit_group;" ::: "memory");
    };

    auto compute_stage = [&](int s) {
        const uint32_t stg = sbase + (uint32_t)s * STAGE_B;
        const uint32_t aHi = stg;
        const uint32_t bHi = stg + (uint32_t)PLANE_H * 2u;
        const uint32_t bLo = stg + (uint32_t)(2 * PLANE_H) * 2u;
#pragma unroll
        for (int ks = 0; ks < 2; ++ks) {
            const int k0 = ks * 16;
            uint32_t ah[4][4], bh[4][2], bl[4][2];
#pragma unroll
            for (int p = 0; p < 2; ++p) {
                const uint32_t off = (uint32_t)((wn + p * 16 + b_r) * PADH + k0 + b_c) * 2u;
                ldsm4(bh[2*p][0], bh[2*p][1], bh[2*p+1][0], bh[2*p+1][1], bHi + off);
                ldsm4(bl[2*p][0], bl[2*p][1], bl[2*p+1][0], bl[2*p+1][1], bLo + off);
            }
#pragma unroll
            for (int mt = 0; mt < 4; ++mt) {
                const uint32_t off = (uint32_t)((wm + mt * 16 + a_r) * PADH + k0 + a_c) * 2u;
                ldsm4(ah[mt][0], ah[mt][1], ah[mt][2], ah[mt][3], aHi + off);
            }
#pragma unroll
            for (int mt = 0; mt < 4; ++mt)
#pragma unroll
                for (int nt = 0; nt < 4; ++nt)
                    mma16816(acc[mt][nt], ah[mt], bh[nt]);
#pragma unroll
            for (int mt = 0; mt < 4; ++mt)
#pragma unroll
                for (int nt = 0; nt < 4; ++nt)
                    mma16816(acc[mt][nt], ah[mt], bl[nt]);
        }
    };

    load_stage(0, 0);
    load_stage(1, 1);
    for (int c = 0; c < NC; ++c) {
        asm volatile("cp.async.wait_group 1;" ::: "memory");
        __syncthreads();
        if (c + 2 < NC) load_stage((c + 2) % 3, c + 2);
        compute_stage(c % 3);
    }

#pragma unroll
    for (int mt = 0; mt < 4; ++mt) {
        const int row0 = bm + wm + mt * 16 + g;
#pragma unroll
        for (int nt = 0; nt < 4; ++nt) {
            const int col = bn + wn + nt * 8 + tig * 2;
            if (col < N) {
                *(float2*)(C + (size_t)row0 * N + col)       = make_float2(acc[mt][nt][0], acc[mt][nt][1]);
                *(float2*)(C + (size_t)(row0 + 8) * N + col) = make_float2(acc[mt][nt][2], acc[mt][nt][3]);
            }
        }
    }
}

// ---------------- depthwise causal conv (width 4) + SiLU ----------------
__global__ void __launch_bounds__(256) conv_silu_kernel(
    const float* __restrict__ cw, const float* __restrict__ cb)
{
    const int c  = blockIdx.x * 256 + threadIdx.x;
    const int b  = blockIdx.z;
    const int t0 = blockIdx.y * 32;

    const float w0 = cw[c*4+0], w1 = cw[c*4+1], w2 = cw[c*4+2], w3 = cw[c*4+3];
    const float bias = cb[c];

    const float* base = g_zx + ((size_t)b * TLEN) * D_IN_PROJ + D_INNER + c;
    float* ob = g_xbc + ((size_t)b * TLEN) * CONV_DIM + c;

    float x0 = (t0 >= 3) ? base[(size_t)(t0-3) * D_IN_PROJ] : 0.f;
    float x1 = (t0 >= 2) ? base[(size_t)(t0-2) * D_IN_PROJ] : 0.f;
    float x2 = (t0 >= 1) ? base[(size_t)(t0-1) * D_IN_PROJ] : 0.f;

    for (int t = t0; t < t0 + 32; ++t) {
        const float x3 = base[(size_t)t * D_IN_PROJ];
        const float v  = bias + x0*w0 + x1*w1 + x2*w2 + x3*w3;
        ob[(size_t)t * CONV_DIM] = v / (1.f + expf(-v));
        x0 = x1; x1 = x2; x2 = x3;
    }
}

// ---------------- SSM scan (PROVEN 128-thread version from R1) ----------------
// One block per (h, b). 128 threads: thread = p*2 + half; each owns h[p][half*64 .. +64).
#define SCAN_TC 8
__global__ void __launch_bounds__(128) scan_kernel(
    const float* __restrict__ dt_bias, const float* __restrict__ A_log,
    const float* __restrict__ Dskip)
{
    const int h   = blockIdx.x;
    const int b   = blockIdx.y;
    const int tid = threadIdx.x;
    const int p    = tid >> 1;
    const int half = tid & 1;
    const int nb   = half * 64;

    __shared__ __align__(16) float sB[SCAN_TC][128];
    __shared__ __align__(16) float sC[SCAN_TC][128];
    __shared__ __align__(16) float sX[SCAN_TC][64];
    __shared__ float sDA[SCAN_TC], sDT[SCAN_TC];

    float4 hst[16];
#pragma unroll
    for (int q = 0; q < 16; ++q) hst[q] = make_float4(0.f,0.f,0.f,0.f);

    const float Acoef = -expf(A_log[h]);
    const float dtb   = dt_bias[h];
    const float dsk   = Dskip[h];

    const float* xbc_b    = g_xbc + (size_t)b * TLEN * CONV_DIM;
    const float* dtr_base = g_zx  + (size_t)b * TLEN * D_IN_PROJ + (D_INNER + CONV_DIM) + h;
    float*       y_base   = g_y   + (size_t)b * TLEN * D_INNER + h * HEADDIM;

    for (int t0 = 0; t0 < TLEN; t0 += SCAN_TC) {
#pragma unroll
        for (int tl = 0; tl < SCAN_TC; ++tl) {
            const float* row = xbc_b + (size_t)(t0 + tl) * CONV_DIM;
            sB[tl][tid] = row[D_INNER + tid];
            sC[tl][tid] = row[D_INNER + D_STATE + tid];
            if (tid < 64) sX[tl][tid] = row[h * HEADDIM + tid];
        }
        if (tid < SCAN_TC) {
            const float raw = dtr_base[(size_t)(t0 + tid) * D_IN_PROJ] + dtb;
            const float dt  = (raw > 20.f) ? raw : log1pf(expf(raw));
            sDT[tid] = dt;
            sDA[tid] = expf(dt * Acoef);
        }
        __syncthreads();

#pragma unroll
        for (int tl = 0; tl < SCAN_TC; ++tl) {
            const float dA  = sDA[tl];
            const float dtx = sDT[tl] * sX[tl][p];
            const float4* B4 = (const float4*)&sB[tl][nb];
            const float4* C4 = (const float4*)&sC[tl][nb];
            float y = 0.f;
#pragma unroll
            for (int q = 0; q < 16; ++q) {
                const float4 bb = B4[q];
                const float4 cc = C4[q];
                hst[q].x = hst[q].x * dA + dtx * bb.x;  y += hst[q].x * cc.x;
                hst[q].y = hst[q].y * dA + dtx * bb.y;  y += hst[q].y * cc.y;
                hst[q].z = hst[q].z * dA + dtx * bb.z;  y += hst[q].z * cc.z;
                hst[q].w = hst[q].w * dA + dtx * bb.w;  y += hst[q].w * cc.w;
            }
            y += __shfl_xor_sync(0xffffffffu, y, 1);
            if (half == 0) {
                y += dsk * sX[tl][p];
                y_base[(size_t)(t0 + tl) * D_INNER + p] = y;
            }
        }
        __syncthreads();
    }
}

// ---------------- gate + RMSNorm, emits fp16 hi plane directly ----------------
__global__ void __launch_bounds__(256) gate_norm_cvt_kernel(
    const float* __restrict__ nw, __half* __restrict__ yhi)
{
    const int row = blockIdx.x;
    const int tid = threadIdx.x;
    const float* zrow = g_zx + (size_t)row * D_IN_PROJ;
    const float* yrow = g_y  + (size_t)row * D_INNER;

    float g[16];
    float ss = 0.f;
#pragma unroll
    for (int i = 0; i < 4; ++i) {
        const int e = i * 1024 + tid * 4;
        const float4 yv = *(const float4*)(yrow + e);
        const float4 zv = *(const float4*)(zrow + e);
        float g0 = yv.x * (zv.x / (1.f + expf(-zv.x)));
        float g1 = yv.y * (zv.y / (1.f + expf(-zv.y)));
        float g2 = yv.z * (zv.z / (1.f + expf(-zv.z)));
        float g3 = yv.w * (zv.w / (1.f + expf(-zv.w)));
        g[i*4+0] = g0; g[i*4+1] = g1; g[i*4+2] = g2; g[i*4+3] = g3;
        ss += g0*g0 + g1*g1 + g2*g2 + g3*g3;
    }

    ss += __shfl_xor_sync(0xffffffffu, ss, 16);
    ss += __shfl_xor_sync(0xffffffffu, ss, 8);
    ss += __shfl_xor_sync(0xffffffffu, ss, 4);
    ss += __shfl_xor_sync(0xffffffffu, ss, 2);
    ss += __shfl_xor_sync(0xffffffffu, ss, 1);
    __shared__ float red[8];
    if ((tid & 31) == 0) red[tid >> 5] = ss;
    __syncthreads();
    float tot = 0.f;
#pragma unroll
    for (int w = 0; w < 8; ++w) tot += red[w];

    const float scale = rsqrtf(tot / (float)D_INNER + RMS_EPS);
#pragma unroll
    for (int i = 0; i < 4; ++i) {
        const int e = i * 1024 + tid * 4;
        const float v0 = g[i*4+0] * scale * nw[e+0];
        const float v1 = g[i*4+1] * scale * nw[e+1];
        const float v2 = g[i*4+2] * scale * nw[e+2];
        const float v3 = g[i*4+3] * scale * nw[e+3];
        __half2* hp = (__half2*)(yhi + (size_t)row * D_INNER + e);
        hp[0] = __halves2half2(__float2half_rn(v0), __float2half_rn(v1));
        hp[1] = __halves2half2(__float2half_rn(v2), __float2half_rn(v3));
    }
}

// ---------------- launch ----------------
extern "C" void kernel_launch(void* const* d_in, const int* in_sizes, int n_in,
                              void* d_out, int out_size)
{
    const float* x          = (const float*)d_in[0];
    const float* in_proj_w  = (const float*)d_in[3];
    const float* conv_w     = (const float*)d_in[4];
    const float* conv_b     = (const float*)d_in[5];
    const float* dt_bias    = (const float*)d_in[6];
    const float* A_log      = (const float*)d_in[7];
    const float* Dskip      = (const float*)d_in[8];
    const float* norm_w     = (const float*)d_in[9];
    const float* out_proj_w = (const float*)d_in[10];
    float* out = (float*)d_out;

    float *zx;
    __half *xc, *w1c, *yc, *w2c;
    cudaGetSymbolAddress((void**)&zx,  g_zx);
    cudaGetSymbolAddress((void**)&xc,  g_xc);
    cudaGetSymbolAddress((void**)&w1c, g_w1c);
    cudaGetSymbolAddress((void**)&yc,  g_yc);
    cudaGetSymbolAddress((void**)&w2c, g_w2c);

    cudaFuncSetAttribute(mma_gemm_f16x2,
                         cudaFuncAttributeMaxDynamicSharedMemorySize, GEMM_SMEM);

    // 0) convert: x -> hi plane; weights -> hi+lo planes
    {
        const int nx = NTOK * D_MODEL / 4;
        cvt_hi_kernel<<<(nx + 255) / 256, 256>>>(x, xc, nx);
        const int nw1 = D_IN_PROJ * D_MODEL / 4;
        cvt_f16x2_kernel<<<(nw1 + 255) / 256, 256>>>(in_proj_w, w1c, w1c + (size_t)D_IN_PROJ * D_MODEL, nw1);
        const int nw2 = D_MODEL * D_INNER / 4;
        cvt_f16x2_kernel<<<(nw2 + 255) / 256, 256>>>(out_proj_w, w2c, w2c + (size_t)D_MODEL * D_INNER, nw2);
    }

    // 1) in_proj: zx[4096, 8512] = x * W1^T
    {
        dim3 grid(NTOK / 128, (D_IN_PROJ + 127) / 128);
        mma_gemm_f16x2<<<grid, 256, GEMM_SMEM>>>(
            xc,
            w1c, w1c + (size_t)D_IN_PROJ * D_MODEL,
            zx, NTOK, D_IN_PROJ, D_MODEL);
    }
    // 2) conv + silu
    {
        dim3 grid(CONV_DIM / 256, TLEN / 32, BATCH);
        conv_silu_kernel<<<grid, 256>>>(conv_w, conv_b);
    }
    // 3) SSM scan (128-thread proven version)
    {
        dim3 grid(NHEADS, BATCH);
        scan_kernel<<<grid, 128>>>(dt_bias, A_log, Dskip);
    }
    // 4) gate + RMSNorm + fp16 hi (fused)
    gate_norm_cvt_kernel<<<NTOK, 256>>>(norm_w, yc);

    // 5) out_proj: out[4096, 2048] = y * W2^T
    {
        dim3 grid(NTOK / 128, D_MODEL / 128);
        mma_gemm_f16x2<<<grid, 256, GEMM_SMEM>>>(
            yc,
            w2c, w2c + (size_t)D_MODEL * D_INNER,
            out, NTOK, D_MODEL, D_INNER);
    }
}

// round 9
// speedup vs baseline: 2.2262x; 1.3159x over previous
#include <cuda_runtime.h>
#include <cuda_fp16.h>
#include <math.h>
#include <stdint.h>

#define D_MODEL   2048
#define D_INNER   4096
#define D_STATE   128
#define HEADDIM   64
#define NHEADS    64
#define CONV_DIM  4352     /* D_INNER + 2*D_STATE */
#define D_IN_PROJ 8512     /* 2*D_INNER + 2*D_STATE + NHEADS */
#define BATCH     2
#define TLEN      2048
#define NTOK      (BATCH*TLEN)   /* 4096 */
#define RMS_EPS   1e-5f

#define SSEG 8
#define TSEG (TLEN / SSEG)       /* 256 */
#define HSTATE (HEADDIM * D_STATE)  /* 8192 */

// ---------------- scratch (device globals; no allocs allowed) ----------------
__device__ float g_zx [(size_t)NTOK * D_IN_PROJ];
__device__ float g_xbc[(size_t)NTOK * CONV_DIM];
__device__ float g_y  [(size_t)NTOK * D_INNER];
__device__ float g_hseg[(size_t)BATCH * NHEADS * SSEG * HSTATE];  // segment boundary states
__device__ float g_sumdt[BATCH * NHEADS * SSEG];

__device__ __half g_xc [(size_t)NTOK * D_MODEL];
__device__ __half g_w1c[(size_t)2 * D_IN_PROJ * D_MODEL];
__device__ __half g_yc [(size_t)NTOK * D_INNER];
__device__ __half g_w2c[(size_t)2 * D_MODEL * D_INNER];

__device__ __forceinline__ uint32_t smem_to_u32(const void* p) {
    uint32_t a;
    asm("{ .reg .u64 t; cvta.to.shared.u64 t, %1; cvt.u32.u64 %0, t; }" : "=r"(a) : "l"(p));
    return a;
}

// ---------------- fp32 -> fp16 hi plane only ----------------
__global__ void __launch_bounds__(256) cvt_hi_kernel(
    const float* __restrict__ src, __half* __restrict__ hi, int n4)
{
    const int i = blockIdx.x * 256 + threadIdx.x;
    if (i >= n4) return;
    const float4 v = ((const float4*)src)[i];
    __half2* hp = (__half2*)(hi + (size_t)i * 4);
    hp[0] = __halves2half2(__float2half_rn(v.x), __float2half_rn(v.y));
    hp[1] = __halves2half2(__float2half_rn(v.z), __float2half_rn(v.w));
}

// ---------------- fp32 -> (hi, lo) fp16 planes (weights) ----------------
__global__ void __launch_bounds__(256) cvt_f16x2_kernel(
    const float* __restrict__ src, __half* __restrict__ hi, __half* __restrict__ lo, int n4)
{
    const int i = blockIdx.x * 256 + threadIdx.x;
    if (i >= n4) return;
    const float4 v = ((const float4*)src)[i];
    __half h0 = __float2half_rn(v.x), h1 = __float2half_rn(v.y);
    __half h2 = __float2half_rn(v.z), h3 = __float2half_rn(v.w);
    __half l0 = __float2half_rn(v.x - __half2float(h0));
    __half l1 = __float2half_rn(v.y - __half2float(h1));
    __half l2 = __float2half_rn(v.z - __half2float(h2));
    __half l3 = __float2half_rn(v.w - __half2float(h3));
    __half2* hp = (__half2*)(hi + (size_t)i * 4);
    __half2* lp = (__half2*)(lo + (size_t)i * 4);
    hp[0] = __halves2half2(h0, h1); hp[1] = __halves2half2(h2, h3);
    lp[0] = __halves2half2(l0, l1); lp[1] = __halves2half2(l2, l3);
}

// ======================= fp16x2 GEMM, 128x128 tile, 2 CTAs/SM =======================
#define PADH 40
#define PLANE_H (128 * PADH)
#define STAGE_B (3 * PLANE_H * 2)          /* Ahi Bhi Blo = 30720 bytes */
#define GEMM_SMEM (2 * STAGE_B)            /* 2 stages = 61440 B -> 2 CTAs/SM */

__device__ __forceinline__ void mma16816(float* c, const uint32_t* a, const uint32_t* b) {
    asm volatile(
        "mma.sync.aligned.m16n8k16.row.col.f32.f16.f16.f32 "
        "{%0,%1,%2,%3}, {%4,%5,%6,%7}, {%8,%9}, {%0,%1,%2,%3};"
        : "+f"(c[0]), "+f"(c[1]), "+f"(c[2]), "+f"(c[3])
        : "r"(a[0]), "r"(a[1]), "r"(a[2]), "r"(a[3]), "r"(b[0]), "r"(b[1]));
}
__device__ __forceinline__ void ldsm4(uint32_t& r0, uint32_t& r1, uint32_t& r2, uint32_t& r3,
                                      uint32_t addr) {
    asm volatile("ldmatrix.sync.aligned.m8n8.x4.shared.b16 {%0,%1,%2,%3}, [%4];"
                 : "=r"(r0), "=r"(r1), "=r"(r2), "=r"(r3) : "r"(addr));
}

__global__ void __launch_bounds__(256, 2) mma_gemm_f16x2(
    const __half* __restrict__ Ahi,
    const __half* __restrict__ Bhi, const __half* __restrict__ Blo,
    float* __restrict__ C, int M, int N, int K)
{
    extern __shared__ __half sh[];
    const int tid  = threadIdx.x;
    const int wid  = tid >> 5;
    const int lane = tid & 31;
    const int g    = lane >> 2;
    const int tig  = lane & 3;
    const int bm   = blockIdx.x * 128;
    const int bn   = blockIdx.y * 128;
    const int wm   = (wid & 1) * 64;
    const int wn   = (wid >> 1) * 32;

    const uint32_t sbase = smem_to_u32(sh);

    const int a_r = lane & 15;
    const int a_c = (lane >> 4) * 8;
    const int b_r = (lane & 7) + ((lane >> 4) << 3);
    const int b_c = ((lane >> 3) & 1) * 8;

    float acc[4][4][4];
#pragma unroll
    for (int mt = 0; mt < 4; ++mt)
#pragma unroll
        for (int nt = 0; nt < 4; ++nt)
#pragma unroll
            for (int q = 0; q < 4; ++q) acc[mt][nt][q] = 0.f;

    const int NC = K >> 5;

    auto load_stage = [&](int s, int c) {
        const int kb = c * 32;
        const uint32_t stg = sbase + (uint32_t)s * STAGE_B;
#pragma unroll
        for (int i = 0; i < 2; ++i) {
            const int f   = tid + 256 * i;
            const int row = f >> 2;
            const int seg = (f & 3) * 8;
            const uint32_t doff = (uint32_t)(row * PADH + seg) * 2u;
            {
                const __half* p = Ahi + (size_t)(bm + row) * K + kb + seg;
                asm volatile("cp.async.cg.shared.global [%0], [%1], 16;"
                             :: "r"(stg + doff), "l"(p) : "memory");
            }
            {
                const int brow = bn + row;
                const int safe = (brow < N) ? brow : 0;
                const uint32_t sz = (brow < N) ? 16u : 0u;
                const __half* p  = Bhi + (size_t)safe * K + kb + seg;
                asm volatile("cp.async.cg.shared.global [%0], [%1], 16, %2;"
                             :: "r"(stg + (uint32_t)PLANE_H * 2u + doff), "l"(p), "r"(sz) : "memory");
                const __half* q2 = Blo + (size_t)safe * K + kb + seg;
                asm volatile("cp.async.cg.shared.global [%0], [%1], 16, %2;"
                             :: "r"(stg + (uint32_t)(2 * PLANE_H) * 2u + doff), "l"(q2), "r"(sz) : "memory");
            }
        }
        asm volatile("cp.async.commit_group;" ::: "memory");
    };

    auto compute_stage = [&](int s) {
        const uint32_t stg = sbase + (uint32_t)s * STAGE_B;
        const uint32_t aHi = stg;
        const uint32_t bHi = stg + (uint32_t)PLANE_H * 2u;
        const uint32_t bLo = stg + (uint32_t)(2 * PLANE_H) * 2u;
#pragma unroll
        for (int ks = 0; ks < 2; ++ks) {
            const int k0 = ks * 16;
            uint32_t ah[4][4], bh[4][2], bl[4][2];
#pragma unroll
            for (int p = 0; p < 2; ++p) {
                const uint32_t off = (uint32_t)((wn + p * 16 + b_r) * PADH + k0 + b_c) * 2u;
                ldsm4(bh[2*p][0], bh[2*p][1], bh[2*p+1][0], bh[2*p+1][1], bHi + off);
                ldsm4(bl[2*p][0], bl[2*p][1], bl[2*p+1][0], bl[2*p+1][1], bLo + off);
            }
#pragma unroll
            for (int mt = 0; mt < 4; ++mt) {
                const uint32_t off = (uint32_t)((wm + mt * 16 + a_r) * PADH + k0 + a_c) * 2u;
                ldsm4(ah[mt][0], ah[mt][1], ah[mt][2], ah[mt][3], aHi + off);
            }
#pragma unroll
            for (int mt = 0; mt < 4; ++mt)
#pragma unroll
                for (int nt = 0; nt < 4; ++nt)
                    mma16816(acc[mt][nt], ah[mt], bh[nt]);
#pragma unroll
            for (int mt = 0; mt < 4; ++mt)
#pragma unroll
                for (int nt = 0; nt < 4; ++nt)
                    mma16816(acc[mt][nt], ah[mt], bl[nt]);
        }
    };

    load_stage(0, 0);
    for (int c = 0; c < NC; ++c) {
        if (c + 1 < NC) {
            load_stage((c + 1) & 1, c + 1);
            asm volatile("cp.async.wait_group 1;" ::: "memory");
        } else {
            asm volatile("cp.async.wait_group 0;" ::: "memory");
        }
        __syncthreads();
        compute_stage(c & 1);
        __syncthreads();
    }

#pragma unroll
    for (int mt = 0; mt < 4; ++mt) {
        const int row0 = bm + wm + mt * 16 + g;
#pragma unroll
        for (int nt = 0; nt < 4; ++nt) {
            const int col = bn + wn + nt * 8 + tig * 2;
            if (col < N) {
                *(float2*)(C + (size_t)row0 * N + col)       = make_float2(acc[mt][nt][0], acc[mt][nt][1]);
                *(float2*)(C + (size_t)(row0 + 8) * N + col) = make_float2(acc[mt][nt][2], acc[mt][nt][3]);
            }
        }
    }
}

// ---------------- depthwise causal conv (width 4) + SiLU ----------------
__global__ void __launch_bounds__(256) conv_silu_kernel(
    const float* __restrict__ cw, const float* __restrict__ cb)
{
    const int c  = blockIdx.x * 256 + threadIdx.x;
    const int b  = blockIdx.z;
    const int t0 = blockIdx.y * 32;

    const float w0 = cw[c*4+0], w1 = cw[c*4+1], w2 = cw[c*4+2], w3 = cw[c*4+3];
    const float bias = cb[c];

    const float* base = g_zx + ((size_t)b * TLEN) * D_IN_PROJ + D_INNER + c;
    float* ob = g_xbc + ((size_t)b * TLEN) * CONV_DIM + c;

    float x0 = (t0 >= 3) ? base[(size_t)(t0-3) * D_IN_PROJ] : 0.f;
    float x1 = (t0 >= 2) ? base[(size_t)(t0-2) * D_IN_PROJ] : 0.f;
    float x2 = (t0 >= 1) ? base[(size_t)(t0-1) * D_IN_PROJ] : 0.f;

    for (int t = t0; t < t0 + 32; ++t) {
        const float x3 = base[(size_t)t * D_IN_PROJ];
        const float v  = bias + x0*w0 + x1*w1 + x2*w2 + x3*w3;
        ob[(size_t)t * CONV_DIM] = v / (1.f + expf(-v));
        x0 = x1; x1 = x2; x2 = x3;
    }
}

// ---------------- segmented SSM scan: pass A (local scans, zero init) ----------------
// grid (NHEADS, BATCH, SSEG), 128 threads (p = tid>>1 head-dim, half = state half).
#define SCAN_TC 8
__global__ void __launch_bounds__(128) scan_seg_kernel(
    const float* __restrict__ dt_bias, const float* __restrict__ A_log,
    const float* __restrict__ Dskip)
{
    const int h   = blockIdx.x;
    const int b   = blockIdx.y;
    const int s   = blockIdx.z;
    const int tid = threadIdx.x;
    const int p    = tid >> 1;
    const int half = tid & 1;
    const int nb   = half * 64;

    __shared__ __align__(16) float sB[SCAN_TC][128];
    __shared__ __align__(16) float sC[SCAN_TC][128];
    __shared__ __align__(16) float sX[SCAN_TC][64];
    __shared__ float sDA[SCAN_TC], sDT[SCAN_TC];
    __shared__ float sred[8];

    float4 hst[16];
#pragma unroll
    for (int q = 0; q < 16; ++q) hst[q] = make_float4(0.f,0.f,0.f,0.f);

    const float Acoef = -expf(A_log[h]);
    const float dtb   = dt_bias[h];
    const float dsk   = Dskip[h];

    const float* xbc_b    = g_xbc + (size_t)b * TLEN * CONV_DIM;
    const float* dtr_base = g_zx  + (size_t)b * TLEN * D_IN_PROJ + (D_INNER + CONV_DIM) + h;
    float*       y_base   = g_y   + (size_t)b * TLEN * D_INNER + h * HEADDIM;

    const int tbeg = s * TSEG;
    float sumdt_part = 0.f;

    for (int t0 = tbeg; t0 < tbeg + TSEG; t0 += SCAN_TC) {
#pragma unroll
        for (int tl = 0; tl < SCAN_TC; ++tl) {
            const float* row = xbc_b + (size_t)(t0 + tl) * CONV_DIM;
            sB[tl][tid] = row[D_INNER + tid];
            sC[tl][tid] = row[D_INNER + D_STATE + tid];
            if (tid < 64) sX[tl][tid] = row[h * HEADDIM + tid];
        }
        if (tid < SCAN_TC) {
            const float raw = dtr_base[(size_t)(t0 + tid) * D_IN_PROJ] + dtb;
            const float dt  = (raw > 20.f) ? raw : log1pf(expf(raw));
            sDT[tid] = dt;
            sDA[tid] = expf(dt * Acoef);
            sumdt_part += dt;
        }
        __syncthreads();

#pragma unroll
        for (int tl = 0; tl < SCAN_TC; ++tl) {
            const float dA  = sDA[tl];
            const float dtx = sDT[tl] * sX[tl][p];
            const float4* B4 = (const float4*)&sB[tl][nb];
            const float4* C4 = (const float4*)&sC[tl][nb];
            float y = 0.f;
#pragma unroll
            for (int q = 0; q < 16; ++q) {
                const float4 bb = B4[q];
                const float4 cc = C4[q];
                hst[q].x = hst[q].x * dA + dtx * bb.x;  y += hst[q].x * cc.x;
                hst[q].y = hst[q].y * dA + dtx * bb.y;  y += hst[q].y * cc.y;
                hst[q].z = hst[q].z * dA + dtx * bb.z;  y += hst[q].z * cc.z;
                hst[q].w = hst[q].w * dA + dtx * bb.w;  y += hst[q].w * cc.w;
            }
            y += __shfl_xor_sync(0xffffffffu, y, 1);
            if (half == 0) {
                y += dsk * sX[tl][p];
                y_base[(size_t)(t0 + tl) * D_INNER + p] = y;
            }
        }
        __syncthreads();
    }

    // write local end state
    float4* dst = (float4*)(g_hseg + ((size_t)((b * NHEADS + h) * SSEG + s)) * HSTATE
                            + p * D_STATE + nb);
#pragma unroll
    for (int q = 0; q < 16; ++q) dst[q] = hst[q];

    // reduce sum of dt over this segment
    if (tid < 8) sred[tid] = sumdt_part;
    __syncthreads();
    if (tid == 0) {
        float t = 0.f;
#pragma unroll
        for (int i = 0; i < 8; ++i) t += sred[i];
        g_sumdt[(b * NHEADS + h) * SSEG + s] = t;
    }
}

// ---------------- pass B: sequential combine of segment boundary states ----------------
// In-place: slot s becomes Hstart_s (true state at segment start).
__global__ void __launch_bounds__(256) seg_combine_kernel(const float* __restrict__ A_log)
{
    const int bh  = blockIdx.x;      // 0..127
    const int h   = bh & (NHEADS - 1);
    const int tid = threadIdx.x;
    const float Acoef = -expf(A_log[h]);

    float4 carry[8];
#pragma unroll
    for (int i = 0; i < 8; ++i) carry[i] = make_float4(0.f,0.f,0.f,0.f);

    float* base = g_hseg + (size_t)bh * SSEG * HSTATE + tid * 32;
#pragma unroll
    for (int s = 0; s < SSEG; ++s) {
        const float P = expf(Acoef * g_sumdt[bh * SSEG + s]);
        float4* slot = (float4*)(base + (size_t)s * HSTATE);
#pragma unroll
        for (int i = 0; i < 8; ++i) {
            const float4 hend = slot[i];
            const float4 old  = carry[i];
            slot[i] = old;   // Hstart_s
            carry[i].x = P * old.x + hend.x;
            carry[i].y = P * old.y + hend.y;
            carry[i].z = P * old.z + hend.z;
            carry[i].w = P * old.w + hend.w;
        }
    }
}

// ---------------- pass C: correction y_t += prefix_t * (C_t . Hstart) ----------------
__global__ void __launch_bounds__(128) seg_correct_kernel(
    const float* __restrict__ dt_bias, const float* __restrict__ A_log)
{
    const int h   = blockIdx.x;
    const int b   = blockIdx.y;
    const int s   = blockIdx.z + 1;            // segment 0 needs no correction
    const int tid = threadIdx.x;
    const int p    = tid >> 1;
    const int half = tid & 1;
    const int nb   = half * 64;

    __shared__ __align__(16) float sC[SCAN_TC][128];
    __shared__ float sDA[SCAN_TC];

    float4 hs[16];
    const float4* src = (const float4*)(g_hseg + ((size_t)((b * NHEADS + h) * SSEG + s)) * HSTATE
                                        + p * D_STATE + nb);
#pragma unroll
    for (int q = 0; q < 16; ++q) hs[q] = src[q];

    const float Acoef = -expf(A_log[h]);
    const float dtb   = dt_bias[h];

    const float* xbc_b    = g_xbc + (size_t)b * TLEN * CONV_DIM;
    const float* dtr_base = g_zx  + (size_t)b * TLEN * D_IN_PROJ + (D_INNER + CONV_DIM) + h;
    float*       y_base   = g_y   + (size_t)b * TLEN * D_INNER + h * HEADDIM;

    float carryP = 1.f;
    const int tbeg = s * TSEG;

    for (int t0 = tbeg; t0 < tbeg + TSEG; t0 += SCAN_TC) {
#pragma unroll
        for (int tl = 0; tl < SCAN_TC; ++tl) {
            const float* row = xbc_b + (size_t)(t0 + tl) * CONV_DIM;
            sC[tl][tid] = row[D_INNER + D_STATE + tid];
        }
        if (tid < SCAN_TC) {
            const float raw = dtr_base[(size_t)(t0 + tid) * D_IN_PROJ] + dtb;
            const float dt  = (raw > 20.f) ? raw : log1pf(expf(raw));
            sDA[tid] = expf(dt * Acoef);
        }
        __syncthreads();

        float pref = carryP;
#pragma unroll
        for (int tl = 0; tl < SCAN_TC; ++tl) {
            pref *= sDA[tl];
            const float4* C4 = (const float4*)&sC[tl][nb];
            float dot = 0.f;
#pragma unroll
            for (int q = 0; q < 16; ++q) {
                const float4 cc = C4[q];
                dot += hs[q].x * cc.x + hs[q].y * cc.y + hs[q].z * cc.z + hs[q].w * cc.w;
            }
            dot += __shfl_xor_sync(0xffffffffu, dot, 1);
            if (half == 0)
                y_base[(size_t)(t0 + tl) * D_INNER + p] += pref * dot;
        }
        carryP = pref;
        __syncthreads();
    }
}

// ---------------- gate + RMSNorm, emits fp16 hi plane directly ----------------
__global__ void __launch_bounds__(256) gate_norm_cvt_kernel(
    const float* __restrict__ nw, __half* __restrict__ yhi)
{
    const int row = blockIdx.x;
    const int tid = threadIdx.x;
    const float* zrow = g_zx + (size_t)row * D_IN_PROJ;
    const float* yrow = g_y  + (size_t)row * D_INNER;

    float g[16];
    float ss = 0.f;
#pragma unroll
    for (int i = 0; i < 4; ++i) {
        const int e = i * 1024 + tid * 4;
        const float4 yv = *(const float4*)(yrow + e);
        const float4 zv = *(const float4*)(zrow + e);
        float g0 = yv.x * (zv.x / (1.f + expf(-zv.x)));
        float g1 = yv.y * (zv.y / (1.f + expf(-zv.y)));
        float g2 = yv.z * (zv.z / (1.f + expf(-zv.z)));
        float g3 = yv.w * (zv.w / (1.f + expf(-zv.w)));
        g[i*4+0] = g0; g[i*4+1] = g1; g[i*4+2] = g2; g[i*4+3] = g3;
        ss += g0*g0 + g1*g1 + g2*g2 + g3*g3;
    }

    ss += __shfl_xor_sync(0xffffffffu, ss, 16);
    ss += __shfl_xor_sync(0xffffffffu, ss, 8);
    ss += __shfl_xor_sync(0xffffffffu, ss, 4);
    ss += __shfl_xor_sync(0xffffffffu, ss, 2);
    ss += __shfl_xor_sync(0xffffffffu, ss, 1);
    __shared__ float red[8];
    if ((tid & 31) == 0) red[tid >> 5] = ss;
    __syncthreads();
    float tot = 0.f;
#pragma unroll
    for (int w = 0; w < 8; ++w) tot += red[w];

    const float scale = rsqrtf(tot / (float)D_INNER + RMS_EPS);
#pragma unroll
    for (int i = 0; i < 4; ++i) {
        const int e = i * 1024 + tid * 4;
        const float v0 = g[i*4+0] * scale * nw[e+0];
        const float v1 = g[i*4+1] * scale * nw[e+1];
        const float v2 = g[i*4+2] * scale * nw[e+2];
        const float v3 = g[i*4+3] * scale * nw[e+3];
        __half2* hp = (__half2*)(yhi + (size_t)row * D_INNER + e);
        hp[0] = __halves2half2(__float2half_rn(v0), __float2half_rn(v1));
        hp[1] = __halves2half2(__float2half_rn(v2), __float2half_rn(v3));
    }
}

// ---------------- launch ----------------
extern "C" void kernel_launch(void* const* d_in, const int* in_sizes, int n_in,
                              void* d_out, int out_size)
{
    const float* x          = (const float*)d_in[0];
    const float* in_proj_w  = (const float*)d_in[3];
    const float* conv_w     = (const float*)d_in[4];
    const float* conv_b     = (const float*)d_in[5];
    const float* dt_bias    = (const float*)d_in[6];
    const float* A_log      = (const float*)d_in[7];
    const float* Dskip      = (const float*)d_in[8];
    const float* norm_w     = (const float*)d_in[9];
    const float* out_proj_w = (const float*)d_in[10];
    float* out = (float*)d_out;

    float *zx;
    __half *xc, *w1c, *yc, *w2c;
    cudaGetSymbolAddress((void**)&zx,  g_zx);
    cudaGetSymbolAddress((void**)&xc,  g_xc);
    cudaGetSymbolAddress((void**)&w1c, g_w1c);
    cudaGetSymbolAddress((void**)&yc,  g_yc);
    cudaGetSymbolAddress((void**)&w2c, g_w2c);

    cudaFuncSetAttribute(mma_gemm_f16x2,
                         cudaFuncAttributeMaxDynamicSharedMemorySize, GEMM_SMEM);

    // 0) convert: x -> hi plane; weights -> hi+lo planes
    {
        const int nx = NTOK * D_MODEL / 4;
        cvt_hi_kernel<<<(nx + 255) / 256, 256>>>(x, xc, nx);
        const int nw1 = D_IN_PROJ * D_MODEL / 4;
        cvt_f16x2_kernel<<<(nw1 + 255) / 256, 256>>>(in_proj_w, w1c, w1c + (size_t)D_IN_PROJ * D_MODEL, nw1);
        const int nw2 = D_MODEL * D_INNER / 4;
        cvt_f16x2_kernel<<<(nw2 + 255) / 256, 256>>>(out_proj_w, w2c, w2c + (size_t)D_MODEL * D_INNER, nw2);
    }

    // 1) in_proj: zx[4096, 8512] = x * W1^T
    {
        dim3 grid(NTOK / 128, (D_IN_PROJ + 127) / 128);
        mma_gemm_f16x2<<<grid, 256, GEMM_SMEM>>>(
            xc, w1c, w1c + (size_t)D_IN_PROJ * D_MODEL,
            zx, NTOK, D_IN_PROJ, D_MODEL);
    }
    // 2) conv + silu
    {
        dim3 grid(CONV_DIM / 256, TLEN / 32, BATCH);
        conv_silu_kernel<<<grid, 256>>>(conv_w, conv_b);
    }
    // 3) segmented SSM scan: local scans -> combine -> correct
    {
        dim3 gridA(NHEADS, BATCH, SSEG);
        scan_seg_kernel<<<gridA, 128>>>(dt_bias, A_log, Dskip);
        seg_combine_kernel<<<BATCH * NHEADS, 256>>>(A_log);
        dim3 gridC(NHEADS, BATCH, SSEG - 1);
        seg_correct_kernel<<<gridC, 128>>>(dt_bias, A_log);
    }
    // 4) gate + RMSNorm + fp16 hi (fused)
    gate_norm_cvt_kernel<<<NTOK, 256>>>(norm_w, yc);

    // 5) out_proj: out[4096, 2048] = y * W2^T
    {
        dim3 grid(NTOK / 128, D_MODEL / 128);
        mma_gemm_f16x2<<<grid, 256, GEMM_SMEM>>>(
            yc, w2c, w2c + (size_t)D_MODEL * D_INNER,
            out, NTOK, D_MODEL, D_INNER);
    }
}

// round 10
// speedup vs baseline: 2.2841x; 1.0260x over previous
#include <cuda_runtime.h>
#include <cuda_fp16.h>
#include <math.h>
#include <stdint.h>

#define D_MODEL   2048
#define D_INNER   4096
#define D_STATE   128
#define HEADDIM   64
#define NHEADS    64
#define CONV_DIM  4352     /* D_INNER + 2*D_STATE */
#define D_IN_PROJ 8512     /* 2*D_INNER + 2*D_STATE + NHEADS */
#define BATCH     2
#define TLEN      2048
#define NTOK      (BATCH*TLEN)   /* 4096 */
#define RMS_EPS   1e-5f

#define SSEG 16
#define TSEG (TLEN / SSEG)       /* 128 */
#define HSTATE (HEADDIM * D_STATE)  /* 8192 */

// ---------------- scratch (device globals; no allocs allowed) ----------------
__device__ float g_zx [(size_t)NTOK * D_IN_PROJ];
__device__ float g_xbc[(size_t)NTOK * CONV_DIM];
__device__ float g_y  [(size_t)NTOK * D_INNER];
__device__ float g_hseg[(size_t)BATCH * NHEADS * SSEG * HSTATE];
__device__ float g_sumdt[BATCH * NHEADS * SSEG];

__device__ __half g_xc [(size_t)NTOK * D_MODEL];
__device__ __half g_w1c[(size_t)2 * D_IN_PROJ * D_MODEL];
__device__ __half g_yc [(size_t)NTOK * D_INNER];
__device__ __half g_w2c[(size_t)2 * D_MODEL * D_INNER];

__device__ __forceinline__ uint32_t smem_to_u32(const void* p) {
    uint32_t a;
    asm("{ .reg .u64 t; cvta.to.shared.u64 t, %1; cvt.u32.u64 %0, t; }" : "=r"(a) : "l"(p));
    return a;
}

// ---------------- fp32 -> fp16 hi plane only ----------------
__global__ void __launch_bounds__(256) cvt_hi_kernel(
    const float* __restrict__ src, __half* __restrict__ hi, int n4)
{
    const int i = blockIdx.x * 256 + threadIdx.x;
    if (i >= n4) return;
    const float4 v = ((const float4*)src)[i];
    __half2* hp = (__half2*)(hi + (size_t)i * 4);
    hp[0] = __halves2half2(__float2half_rn(v.x), __float2half_rn(v.y));
    hp[1] = __halves2half2(__float2half_rn(v.z), __float2half_rn(v.w));
}

// ---------------- fp32 -> (hi, lo) fp16 planes (weights) ----------------
__global__ void __launch_bounds__(256) cvt_f16x2_kernel(
    const float* __restrict__ src, __half* __restrict__ hi, __half* __restrict__ lo, int n4)
{
    const int i = blockIdx.x * 256 + threadIdx.x;
    if (i >= n4) return;
    const float4 v = ((const float4*)src)[i];
    __half h0 = __float2half_rn(v.x), h1 = __float2half_rn(v.y);
    __half h2 = __float2half_rn(v.z), h3 = __float2half_rn(v.w);
    __half l0 = __float2half_rn(v.x - __half2float(h0));
    __half l1 = __float2half_rn(v.y - __half2float(h1));
    __half l2 = __float2half_rn(v.z - __half2float(h2));
    __half l3 = __float2half_rn(v.w - __half2float(h3));
    __half2* hp = (__half2*)(hi + (size_t)i * 4);
    __half2* lp = (__half2*)(lo + (size_t)i * 4);
    hp[0] = __halves2half2(h0, h1); hp[1] = __halves2half2(h2, h3);
    lp[0] = __halves2half2(l0, l1); lp[1] = __halves2half2(l2, l3);
}

// ======== fp16x2 GEMM: 128x128 tile, 3-stage pipeline, 2 CTAs/SM ========
#define PADH 40
#define PLANE_H (128 * PADH)
#define STAGE_B (3 * PLANE_H * 2)          /* Ahi Bhi Blo = 30720 bytes */
#define GEMM_SMEM (3 * STAGE_B)            /* 92160 B; x2 CTAs = 184320 <= 228KB */

__device__ __forceinline__ void mma16816(float* c, const uint32_t* a, const uint32_t* b) {
    asm volatile(
        "mma.sync.aligned.m16n8k16.row.col.f32.f16.f16.f32 "
        "{%0,%1,%2,%3}, {%4,%5,%6,%7}, {%8,%9}, {%0,%1,%2,%3};"
        : "+f"(c[0]), "+f"(c[1]), "+f"(c[2]), "+f"(c[3])
        : "r"(a[0]), "r"(a[1]), "r"(a[2]), "r"(a[3]), "r"(b[0]), "r"(b[1]));
}
__device__ __forceinline__ void ldsm4(uint32_t& r0, uint32_t& r1, uint32_t& r2, uint32_t& r3,
                                      uint32_t addr) {
    asm volatile("ldmatrix.sync.aligned.m8n8.x4.shared.b16 {%0,%1,%2,%3}, [%4];"
                 : "=r"(r0), "=r"(r1), "=r"(r2), "=r"(r3) : "r"(addr));
}

__global__ void __launch_bounds__(256, 2) mma_gemm_f16x2(
    const __half* __restrict__ Ahi,
    const __half* __restrict__ Bhi, const __half* __restrict__ Blo,
    float* __restrict__ C, int M, int N, int K)
{
    extern __shared__ __half sh[];
    const int tid  = threadIdx.x;
    const int wid  = tid >> 5;
    const int lane = tid & 31;
    const int g    = lane >> 2;
    const int tig  = lane & 3;
    const int bm   = blockIdx.x * 128;
    const int bn   = blockIdx.y * 128;
    const int wm   = (wid & 1) * 64;
    const int wn   = (wid >> 1) * 32;

    const uint32_t sbase = smem_to_u32(sh);

    const int a_r = lane & 15;
    const int a_c = (lane >> 4) * 8;
    const int b_r = (lane & 7) + ((lane >> 4) << 3);
    const int b_c = ((lane >> 3) & 1) * 8;

    float acc[4][4][4];
#pragma unroll
    for (int mt = 0; mt < 4; ++mt)
#pragma unroll
        for (int nt = 0; nt < 4; ++nt)
#pragma unroll
            for (int q = 0; q < 4; ++q) acc[mt][nt][q] = 0.f;

    const int NC = K >> 5;

    auto load_stage = [&](int s, int c) {
        const int kb = c * 32;
        const uint32_t stg = sbase + (uint32_t)s * STAGE_B;
#pragma unroll
        for (int i = 0; i < 2; ++i) {
            const int f   = tid + 256 * i;
            const int row = f >> 2;
            const int seg = (f & 3) * 8;
            const uint32_t doff = (uint32_t)(row * PADH + seg) * 2u;
            {
                const __half* p = Ahi + (size_t)(bm + row) * K + kb + seg;
                asm volatile("cp.async.cg.shared.global [%0], [%1], 16;"
                             :: "r"(stg + doff), "l"(p) : "memory");
            }
            {
                const int brow = bn + row;
                const int safe = (brow < N) ? brow : 0;
                const uint32_t sz = (brow < N) ? 16u : 0u;
                const __half* p  = Bhi + (size_t)safe * K + kb + seg;
                asm volatile("cp.async.cg.shared.global [%0], [%1], 16, %2;"
                             :: "r"(stg + (uint32_t)PLANE_H * 2u + doff), "l"(p), "r"(sz) : "memory");
                const __half* q2 = Blo + (size_t)safe * K + kb + seg;
                asm volatile("cp.async.cg.shared.global [%0], [%1], 16, %2;"
                             :: "r"(stg + (uint32_t)(2 * PLANE_H) * 2u + doff), "l"(q2), "r"(sz) : "memory");
            }
        }
        asm volatile("cp.async.commit_group;" ::: "memory");
    };

    auto compute_stage = [&](int s) {
        const uint32_t stg = sbase + (uint32_t)s * STAGE_B;
        const uint32_t aHi = stg;
        const uint32_t bHi = stg + (uint32_t)PLANE_H * 2u;
        const uint32_t bLo = stg + (uint32_t)(2 * PLANE_H) * 2u;
#pragma unroll
        for (int ks = 0; ks < 2; ++ks) {
            const int k0 = ks * 16;
            uint32_t ah[4][4], bh[4][2], bl[4][2];
#pragma unroll
            for (int p = 0; p < 2; ++p) {
                const uint32_t off = (uint32_t)((wn + p * 16 + b_r) * PADH + k0 + b_c) * 2u;
                ldsm4(bh[2*p][0], bh[2*p][1], bh[2*p+1][0], bh[2*p+1][1], bHi + off);
                ldsm4(bl[2*p][0], bl[2*p][1], bl[2*p+1][0], bl[2*p+1][1], bLo + off);
            }
#pragma unroll
            for (int mt = 0; mt < 4; ++mt) {
                const uint32_t off = (uint32_t)((wm + mt * 16 + a_r) * PADH + k0 + a_c) * 2u;
                ldsm4(ah[mt][0], ah[mt][1], ah[mt][2], ah[mt][3], aHi + off);
            }
#pragma unroll
            for (int mt = 0; mt < 4; ++mt)
#pragma unroll
                for (int nt = 0; nt < 4; ++nt)
                    mma16816(acc[mt][nt], ah[mt], bh[nt]);
#pragma unroll
            for (int mt = 0; mt < 4; ++mt)
#pragma unroll
                for (int nt = 0; nt < 4; ++nt)
                    mma16816(acc[mt][nt], ah[mt], bl[nt]);
        }
    };

    // 3-stage pipeline, one barrier per chunk
    load_stage(0, 0);
    load_stage(1, 1);
    for (int c = 0; c < NC; ++c) {
        if (c + 2 < NC) {
            asm volatile("cp.async.wait_group 1;" ::: "memory");
        } else {
            asm volatile("cp.async.wait_group 0;" ::: "memory");
        }
        __syncthreads();
        if (c + 2 < NC) load_stage((c + 2) % 3, c + 2);
        compute_stage(c % 3);
    }

#pragma unroll
    for (int mt = 0; mt < 4; ++mt) {
        const int row0 = bm + wm + mt * 16 + g;
#pragma unroll
        for (int nt = 0; nt < 4; ++nt) {
            const int col = bn + wn + nt * 8 + tig * 2;
            if (col < N) {
                *(float2*)(C + (size_t)row0 * N + col)       = make_float2(acc[mt][nt][0], acc[mt][nt][1]);
                *(float2*)(C + (size_t)(row0 + 8) * N + col) = make_float2(acc[mt][nt][2], acc[mt][nt][3]);
            }
        }
    }
}

// ---------------- depthwise causal conv (width 4) + SiLU ----------------
__global__ void __launch_bounds__(256) conv_silu_kernel(
    const float* __restrict__ cw, const float* __restrict__ cb)
{
    const int c  = blockIdx.x * 256 + threadIdx.x;
    const int b  = blockIdx.z;
    const int t0 = blockIdx.y * 32;

    const float w0 = cw[c*4+0], w1 = cw[c*4+1], w2 = cw[c*4+2], w3 = cw[c*4+3];
    const float bias = cb[c];

    const float* base = g_zx + ((size_t)b * TLEN) * D_IN_PROJ + D_INNER + c;
    float* ob = g_xbc + ((size_t)b * TLEN) * CONV_DIM + c;

    float x0 = (t0 >= 3) ? base[(size_t)(t0-3) * D_IN_PROJ] : 0.f;
    float x1 = (t0 >= 2) ? base[(size_t)(t0-2) * D_IN_PROJ] : 0.f;
    float x2 = (t0 >= 1) ? base[(size_t)(t0-1) * D_IN_PROJ] : 0.f;

    for (int t = t0; t < t0 + 32; ++t) {
        const float x3 = base[(size_t)t * D_IN_PROJ];
        const float v  = bias + x0*w0 + x1*w1 + x2*w2 + x3*w3;
        ob[(size_t)t * CONV_DIM] = v / (1.f + expf(-v));
        x0 = x1; x1 = x2; x2 = x3;
    }
}

// ---------------- segmented SSM scan: pass A (local scans, zero init) ----------------
#define SCAN_TC 8
__global__ void __launch_bounds__(128) scan_seg_kernel(
    const float* __restrict__ dt_bias, const float* __restrict__ A_log,
    const float* __restrict__ Dskip)
{
    const int h   = blockIdx.x;
    const int b   = blockIdx.y;
    const int s   = blockIdx.z;
    const int tid = threadIdx.x;
    const int p    = tid >> 1;
    const int half = tid & 1;
    const int nb   = half * 64;

    __shared__ __align__(16) float sB[SCAN_TC][128];
    __shared__ __align__(16) float sC[SCAN_TC][128];
    __shared__ __align__(16) float sX[SCAN_TC][64];
    __shared__ float sDA[SCAN_TC], sDT[SCAN_TC];
    __shared__ float sred[8];

    float4 hst[16];
#pragma unroll
    for (int q = 0; q < 16; ++q) hst[q] = make_float4(0.f,0.f,0.f,0.f);

    const float Acoef = -expf(A_log[h]);
    const float dtb   = dt_bias[h];
    const float dsk   = Dskip[h];

    const float* xbc_b    = g_xbc + (size_t)b * TLEN * CONV_DIM;
    const float* dtr_base = g_zx  + (size_t)b * TLEN * D_IN_PROJ + (D_INNER + CONV_DIM) + h;
    float*       y_base   = g_y   + (size_t)b * TLEN * D_INNER + h * HEADDIM;

    const int tbeg = s * TSEG;
    float sumdt_part = 0.f;

    for (int t0 = tbeg; t0 < tbeg + TSEG; t0 += SCAN_TC) {
#pragma unroll
        for (int tl = 0; tl < SCAN_TC; ++tl) {
            const float* row = xbc_b + (size_t)(t0 + tl) * CONV_DIM;
            sB[tl][tid] = row[D_INNER + tid];
            sC[tl][tid] = row[D_INNER + D_STATE + tid];
            if (tid < 64) sX[tl][tid] = row[h * HEADDIM + tid];
        }
        if (tid < SCAN_TC) {
            const float raw = dtr_base[(size_t)(t0 + tid) * D_IN_PROJ] + dtb;
            const float dt  = (raw > 20.f) ? raw : log1pf(expf(raw));
            sDT[tid] = dt;
            sDA[tid] = expf(dt * Acoef);
            sumdt_part += dt;
        }
        __syncthreads();

#pragma unroll
        for (int tl = 0; tl < SCAN_TC; ++tl) {
            const float dA  = sDA[tl];
            const float dtx = sDT[tl] * sX[tl][p];
            const float4* B4 = (const float4*)&sB[tl][nb];
            const float4* C4 = (const float4*)&sC[tl][nb];
            // tree-reduce y into 4 partials: dependent chain 64 -> 16 (+2 combine)
            float y0 = 0.f, y1 = 0.f, y2 = 0.f, y3 = 0.f;
#pragma unroll
            for (int q = 0; q < 16; ++q) {
                const float4 bb = B4[q];
                const float4 cc = C4[q];
                hst[q].x = hst[q].x * dA + dtx * bb.x;  y0 += hst[q].x * cc.x;
                hst[q].y = hst[q].y * dA + dtx * bb.y;  y1 += hst[q].y * cc.y;
                hst[q].z = hst[q].z * dA + dtx * bb.z;  y2 += hst[q].z * cc.z;
                hst[q].w = hst[q].w * dA + dtx * bb.w;  y3 += hst[q].w * cc.w;
            }
            float y = (y0 + y1) + (y2 + y3);
            y += __shfl_xor_sync(0xffffffffu, y, 1);
            if (half == 0) {
                y += dsk * sX[tl][p];
                y_base[(size_t)(t0 + tl) * D_INNER + p] = y;
            }
        }
        __syncthreads();
    }

    float4* dst = (float4*)(g_hseg + ((size_t)((b * NHEADS + h) * SSEG + s)) * HSTATE
                            + p * D_STATE + nb);
#pragma unroll
    for (int q = 0; q < 16; ++q) dst[q] = hst[q];

    if (tid < 8) sred[tid] = sumdt_part;
    __syncthreads();
    if (tid == 0) {
        float t = 0.f;
#pragma unroll
        for (int i = 0; i < 8; ++i) t += sred[i];
        g_sumdt[(b * NHEADS + h) * SSEG + s] = t;
    }
}

// ---------------- pass B: sequential combine of segment boundary states ----------------
__global__ void __launch_bounds__(256) seg_combine_kernel(const float* __restrict__ A_log)
{
    const int bh  = blockIdx.x;
    const int h   = bh & (NHEADS - 1);
    const int tid = threadIdx.x;
    const float Acoef = -expf(A_log[h]);

    float4 carry[8];
#pragma unroll
    for (int i = 0; i < 8; ++i) carry[i] = make_float4(0.f,0.f,0.f,0.f);

    float* base = g_hseg + (size_t)bh * SSEG * HSTATE + tid * 32;
#pragma unroll
    for (int s = 0; s < SSEG; ++s) {
        const float P = expf(Acoef * g_sumdt[bh * SSEG + s]);
        float4* slot = (float4*)(base + (size_t)s * HSTATE);
#pragma unroll
        for (int i = 0; i < 8; ++i) {
            const float4 hend = slot[i];
            const float4 old  = carry[i];
            slot[i] = old;
            carry[i].x = P * old.x + hend.x;
            carry[i].y = P * old.y + hend.y;
            carry[i].z = P * old.z + hend.z;
            carry[i].w = P * old.w + hend.w;
        }
    }
}

// ---------------- pass C: correction y_t += prefix_t * (C_t . Hstart) ----------------
__global__ void __launch_bounds__(128) seg_correct_kernel(
    const float* __restrict__ dt_bias, const float* __restrict__ A_log)
{
    const int h   = blockIdx.x;
    const int b   = blockIdx.y;
    const int s   = blockIdx.z + 1;
    const int tid = threadIdx.x;
    const int p    = tid >> 1;
    const int half = tid & 1;
    const int nb   = half * 64;

    __shared__ __align__(16) float sC[SCAN_TC][128];
    __shared__ float sDA[SCAN_TC];

    float4 hs[16];
    const float4* src = (const float4*)(g_hseg + ((size_t)((b * NHEADS + h) * SSEG + s)) * HSTATE
                                        + p * D_STATE + nb);
#pragma unroll
    for (int q = 0; q < 16; ++q) hs[q] = src[q];

    const float Acoef = -expf(A_log[h]);
    const float dtb   = dt_bias[h];

    const float* xbc_b    = g_xbc + (size_t)b * TLEN * CONV_DIM;
    const float* dtr_base = g_zx  + (size_t)b * TLEN * D_IN_PROJ + (D_INNER + CONV_DIM) + h;
    float*       y_base   = g_y   + (size_t)b * TLEN * D_INNER + h * HEADDIM;

    float carryP = 1.f;
    const int tbeg = s * TSEG;

    for (int t0 = tbeg; t0 < tbeg + TSEG; t0 += SCAN_TC) {
#pragma unroll
        for (int tl = 0; tl < SCAN_TC; ++tl) {
            const float* row = xbc_b + (size_t)(t0 + tl) * CONV_DIM;
            sC[tl][tid] = row[D_INNER + D_STATE + tid];
        }
        if (tid < SCAN_TC) {
            const float raw = dtr_base[(size_t)(t0 + tid) * D_IN_PROJ] + dtb;
            const float dt  = (raw > 20.f) ? raw : log1pf(expf(raw));
            sDA[tid] = expf(dt * Acoef);
        }
        __syncthreads();

        float pref = carryP;
#pragma unroll
        for (int tl = 0; tl < SCAN_TC; ++tl) {
            pref *= sDA[tl];
            const float4* C4 = (const float4*)&sC[tl][nb];
            float d0 = 0.f, d1 = 0.f, d2 = 0.f, d3 = 0.f;
#pragma unroll
            for (int q = 0; q < 16; ++q) {
                const float4 cc = C4[q];
                d0 += hs[q].x * cc.x;  d1 += hs[q].y * cc.y;
                d2 += hs[q].z * cc.z;  d3 += hs[q].w * cc.w;
            }
            float dot = (d0 + d1) + (d2 + d3);
            dot += __shfl_xor_sync(0xffffffffu, dot, 1);
            if (half == 0)
                y_base[(size_t)(t0 + tl) * D_INNER + p] += pref * dot;
        }
        carryP = pref;
        __syncthreads();
    }
}

// ---------------- gate + RMSNorm, emits fp16 hi plane directly ----------------
__global__ void __launch_bounds__(256) gate_norm_cvt_kernel(
    const float* __restrict__ nw, __half* __restrict__ yhi)
{
    const int row = blockIdx.x;
    const int tid = threadIdx.x;
    const float* zrow = g_zx + (size_t)row * D_IN_PROJ;
    const float* yrow = g_y  + (size_t)row * D_INNER;

    float g[16];
    float ss = 0.f;
#pragma unroll
    for (int i = 0; i < 4; ++i) {
        const int e = i * 1024 + tid * 4;
        const float4 yv = *(const float4*)(yrow + e);
        const float4 zv = *(const float4*)(zrow + e);
        float g0 = yv.x * (zv.x / (1.f + expf(-zv.x)));
        float g1 = yv.y * (zv.y / (1.f + expf(-zv.y)));
        float g2 = yv.z * (zv.z / (1.f + expf(-zv.z)));
        float g3 = yv.w * (zv.w / (1.f + expf(-zv.w)));
        g[i*4+0] = g0; g[i*4+1] = g1; g[i*4+2] = g2; g[i*4+3] = g3;
        ss += g0*g0 + g1*g1 + g2*g2 + g3*g3;
    }

    ss += __shfl_xor_sync(0xffffffffu, ss, 16);
    ss += __shfl_xor_sync(0xffffffffu, ss, 8);
    ss += __shfl_xor_sync(0xffffffffu, ss, 4);
    ss += __shfl_xor_sync(0xffffffffu, ss, 2);
    ss += __shfl_xor_sync(0xffffffffu, ss, 1);
    __shared__ float red[8];
    if ((tid & 31) == 0) red[tid >> 5] = ss;
    __syncthreads();
    float tot = 0.f;
#pragma unroll
    for (int w = 0; w < 8; ++w) tot += red[w];

    const float scale = rsqrtf(tot / (float)D_INNER + RMS_EPS);
#pragma unroll
    for (int i = 0; i < 4; ++i) {
        const int e = i * 1024 + tid * 4;
        const float v0 = g[i*4+0] * scale * nw[e+0];
        const float v1 = g[i*4+1] * scale * nw[e+1];
        const float v2 = g[i*4+2] * scale * nw[e+2];
        const float v3 = g[i*4+3] * scale * nw[e+3];
        __half2* hp = (__half2*)(yhi + (size_t)row * D_INNER + e);
        hp[0] = __halves2half2(__float2half_rn(v0), __float2half_rn(v1));
        hp[1] = __halves2half2(__float2half_rn(v2), __float2half_rn(v3));
    }
}

// ---------------- launch ----------------
extern "C" void kernel_launch(void* const* d_in, const int* in_sizes, int n_in,
                              void* d_out, int out_size)
{
    const float* x          = (const float*)d_in[0];
    const float* in_proj_w  = (const float*)d_in[3];
    const float* conv_w     = (const float*)d_in[4];
    const float* conv_b     = (const float*)d_in[5];
    const float* dt_bias    = (const float*)d_in[6];
    const float* A_log      = (const float*)d_in[7];
    const float* Dskip      = (const float*)d_in[8];
    const float* norm_w     = (const float*)d_in[9];
    const float* out_proj_w = (const float*)d_in[10];
    float* out = (float*)d_out;

    float *zx;
    __half *xc, *w1c, *yc, *w2c;
    cudaGetSymbolAddress((void**)&zx,  g_zx);
    cudaGetSymbolAddress((void**)&xc,  g_xc);
    cudaGetSymbolAddress((void**)&w1c, g_w1c);
    cudaGetSymbolAddress((void**)&yc,  g_yc);
    cudaGetSymbolAddress((void**)&w2c, g_w2c);

    cudaFuncSetAttribute(mma_gemm_f16x2,
                         cudaFuncAttributeMaxDynamicSharedMemorySize, GEMM_SMEM);

    // 0) convert: x -> hi plane; weights -> hi+lo planes
    {
        const int nx = NTOK * D_MODEL / 4;
        cvt_hi_kernel<<<(nx + 255) / 256, 256>>>(x, xc, nx);
        const int nw1 = D_IN_PROJ * D_MODEL / 4;
        cvt_f16x2_kernel<<<(nw1 + 255) / 256, 256>>>(in_proj_w, w1c, w1c + (size_t)D_IN_PROJ * D_MODEL, nw1);
        const int nw2 = D_MODEL * D_INNER / 4;
        cvt_f16x2_kernel<<<(nw2 + 255) / 256, 256>>>(out_proj_w, w2c, w2c + (size_t)D_MODEL * D_INNER, nw2);
    }

    // 1) in_proj: zx[4096, 8512] = x * W1^T
    {
        dim3 grid(NTOK / 128, (D_IN_PROJ + 127) / 128);
        mma_gemm_f16x2<<<grid, 256, GEMM_SMEM>>>(
            xc, w1c, w1c + (size_t)D_IN_PROJ * D_MODEL,
            zx, NTOK, D_IN_PROJ, D_MODEL);
    }
    // 2) conv + silu
    {
        dim3 grid(CONV_DIM / 256, TLEN / 32, BATCH);
        conv_silu_kernel<<<grid, 256>>>(conv_w, conv_b);
    }
    // 3) segmented SSM scan: local scans -> combine -> correct
    {
        dim3 gridA(NHEADS, BATCH, SSEG);
        scan_seg_kernel<<<gridA, 128>>>(dt_bias, A_log, Dskip);
        seg_combine_kernel<<<BATCH * NHEADS, 256>>>(A_log);
        dim3 gridC(NHEADS, BATCH, SSEG - 1);
        seg_correct_kernel<<<gridC, 128>>>(dt_bias, A_log);
    }
    // 4) gate + RMSNorm + fp16 hi (fused)
    gate_norm_cvt_kernel<<<NTOK, 256>>>(norm_w, yc);

    // 5) out_proj: out[4096, 2048] = y * W2^T
    {
        dim3 grid(NTOK / 128, D_MODEL / 128);
        mma_gemm_f16x2<<<grid, 256, GEMM_SMEM>>>(
            yc, w2c, w2c + (size_t)D_MODEL * D_INNER,
            out, NTOK, D_MODEL, D_INNER);
    }
}